// round 15
// baseline (speedup 1.0000x reference)
#include <cuda_runtime.h>
#include <cuda_bf16.h>
#include <cstdint>
#include <math.h>

// ---------------- constants ----------------
#define TT   2048
#define DD   1024
#define HH   16
#define HS   64
#define EE   8
#define KK   2
#define LL   2
#define CAP  512
#define FF   4096   // 4*D

// ---------------- scratch (device globals; no allocation allowed) ----------
__device__ float g_x  [TT * DD];
__device__ float g_xn [TT * DD];
__device__ float g_qkv[TT * 3 * DD];
__device__ float g_av [TT * DD];
__device__ float g_de [EE * CAP * DD];
__device__ float g_h  [EE * CAP * FF];
__device__ float g_eo [EE * CAP * DD];
__device__ int   g_topi[TT * KK];
__device__ int   g_pos [TT * KK];
__device__ float g_gate[TT * KK];

// ---------------- packed f32x2 helpers ----------------
typedef unsigned long long ull;
__device__ __forceinline__ ull pack2(float lo, float hi) {
    ull r;
    asm("mov.b64 %0, {%1, %2};" : "=l"(r) : "f"(lo), "f"(hi));
    return r;
}
__device__ __forceinline__ void unpack2(ull v, float& lo, float& hi) {
    asm("mov.b64 {%0, %1}, %2;" : "=f"(lo), "=f"(hi) : "l"(v));
}
__device__ __forceinline__ void fma2(ull& d, ull a, ull b) {
    asm("fma.rn.f32x2 %0, %1, %2, %0;" : "+l"(d) : "l"(a), "l"(b));
}
__device__ __forceinline__ void mul2(ull& d, ull a) {
    asm("mul.rn.f32x2 %0, %0, %1;" : "+l"(d) : "l"(a));
}

__device__ __forceinline__ uint32_t smem_u32(const void* p) {
    uint32_t a;
    asm("{ .reg .u64 t; cvta.to.shared.u64 t, %1; cvt.u32.u64 %0, t; }" : "=r"(a) : "l"(p));
    return a;
}

// cp.async 16B (sm_80+ baseline PTX; fine for compute_103)
#define CP_ASYNC16(saddr, gptr)                                                 \
    asm volatile("cp.async.ca.shared.global [%0], [%1], 16;"                    \
        :: "r"(saddr), "l"(gptr) : "memory")
#define CP_COMMIT() asm volatile("cp.async.commit_group;" ::: "memory")
#define CP_WAIT(n)  asm volatile("cp.async.wait_group %0;" :: "n"(n) : "memory")

// =====================================================================
// fp32 GEMM, packed f32x2 FMA, double-buffered (bitwise == round 3 ->
// router decisions preserved). C = A(MxK)*B(NxK)^T (+bias)(+res)(relu).
// =====================================================================
template <bool RELU, bool RES>
__global__ __launch_bounds__(256)
void gemm_kernel(const float* __restrict__ A, const float* __restrict__ Bm,
                 const float* __restrict__ bias, const float* res,
                 float* C,
                 int M, int N, int Kd,
                 long long aB, long long bB, long long biasB, long long cB) {
    int bz = blockIdx.z;
    A  += (long long)bz * aB;
    Bm += (long long)bz * bB;
    C  += (long long)bz * cB;
    if (bias) bias += (long long)bz * biasB;

    int rowBase = blockIdx.y * 128;
    int colBase = blockIdx.x * 128;

    __shared__ float As[2][16][128];
    __shared__ float Bs[2][16][128];

    int tid = threadIdx.x;
    int tx = tid & 15, ty = tid >> 4;
    int lrow = tid >> 2;
    int lcol = (tid & 3) * 4;

    const float* Arow0 = A  + (size_t)(rowBase + lrow)      * Kd + lcol;
    const float* Arow1 = A  + (size_t)(rowBase + lrow + 64) * Kd + lcol;
    const float* Brow0 = Bm + (size_t)(colBase + lrow)      * Kd + lcol;
    const float* Brow1 = Bm + (size_t)(colBase + lrow + 64) * Kd + lcol;

    ull acc2[8][4];
#pragma unroll
    for (int i = 0; i < 8; i++)
#pragma unroll
        for (int j = 0; j < 4; j++) acc2[i][j] = 0ULL;

    float4 ra0, ra1, rb0, rb1;

    ra0 = *(const float4*)(Arow0);
    ra1 = *(const float4*)(Arow1);
    rb0 = *(const float4*)(Brow0);
    rb1 = *(const float4*)(Brow1);
    {
        float* a0 = &As[0][lcol][lrow];
        a0[0 * 128] = ra0.x; a0[1 * 128] = ra0.y; a0[2 * 128] = ra0.z; a0[3 * 128] = ra0.w;
        float* a1 = &As[0][lcol][lrow + 64];
        a1[0 * 128] = ra1.x; a1[1 * 128] = ra1.y; a1[2 * 128] = ra1.z; a1[3 * 128] = ra1.w;
        float* b0 = &Bs[0][lcol][lrow];
        b0[0 * 128] = rb0.x; b0[1 * 128] = rb0.y; b0[2 * 128] = rb0.z; b0[3 * 128] = rb0.w;
        float* b1 = &Bs[0][lcol][lrow + 64];
        b1[0 * 128] = rb1.x; b1[1 * 128] = rb1.y; b1[2 * 128] = rb1.z; b1[3 * 128] = rb1.w;
    }
    __syncthreads();

    const int nCh = Kd >> 4;
    for (int ch = 0; ch < nCh; ++ch) {
        int cur = ch & 1;
        if (ch + 1 < nCh) {
            int k0 = (ch + 1) << 4;
            ra0 = *(const float4*)(Arow0 + k0);
            ra1 = *(const float4*)(Arow1 + k0);
            rb0 = *(const float4*)(Brow0 + k0);
            rb1 = *(const float4*)(Brow1 + k0);
        }
#pragma unroll
        for (int kk = 0; kk < 16; kk++) {
            float4 a0 = *(const float4*)&As[cur][kk][ty * 4];
            float4 a1 = *(const float4*)&As[cur][kk][64 + ty * 4];
            ulonglong2 bb0 = *(const ulonglong2*)&Bs[cur][kk][tx * 4];
            ulonglong2 bb1 = *(const ulonglong2*)&Bs[cur][kk][64 + tx * 4];
            float ar[8] = {a0.x, a0.y, a0.z, a0.w, a1.x, a1.y, a1.z, a1.w};
            ull b2[4] = {bb0.x, bb0.y, bb1.x, bb1.y};
#pragma unroll
            for (int i = 0; i < 8; i++) {
                ull a2 = pack2(ar[i], ar[i]);
#pragma unroll
                for (int j = 0; j < 4; j++) fma2(acc2[i][j], a2, b2[j]);
            }
        }
        if (ch + 1 < nCh) {
            int nxt = cur ^ 1;
            float* a0 = &As[nxt][lcol][lrow];
            a0[0 * 128] = ra0.x; a0[1 * 128] = ra0.y; a0[2 * 128] = ra0.z; a0[3 * 128] = ra0.w;
            float* a1 = &As[nxt][lcol][lrow + 64];
            a1[0 * 128] = ra1.x; a1[1 * 128] = ra1.y; a1[2 * 128] = ra1.z; a1[3 * 128] = ra1.w;
            float* b0 = &Bs[nxt][lcol][lrow];
            b0[0 * 128] = rb0.x; b0[1 * 128] = rb0.y; b0[2 * 128] = rb0.z; b0[3 * 128] = rb0.w;
            float* b1 = &Bs[nxt][lcol][lrow + 64];
            b1[0 * 128] = rb1.x; b1[1 * 128] = rb1.y; b1[2 * 128] = rb1.z; b1[3 * 128] = rb1.w;
            __syncthreads();
        }
    }

#pragma unroll
    for (int i = 0; i < 8; i++) {
        int r = rowBase + ((i < 4) ? (ty * 4 + i) : (64 + ty * 4 + (i - 4)));
#pragma unroll
        for (int jj = 0; jj < 2; jj++) {
            int c = colBase + jj * 64 + tx * 4;
            float4 v;
            unpack2(acc2[i][jj * 2 + 0], v.x, v.y);
            unpack2(acc2[i][jj * 2 + 1], v.z, v.w);
            if (bias) {
                v.x += bias[c]; v.y += bias[c + 1];
                v.z += bias[c + 2]; v.w += bias[c + 3];
            }
            if (RES) {
                float4 rv = *(const float4*)(res + (size_t)r * N + c);
                v.x = rv.x + v.x; v.y = rv.y + v.y;
                v.z = rv.z + v.z; v.w = rv.w + v.w;
            }
            if (RELU) {
                v.x = fmaxf(v.x, 0.f); v.y = fmaxf(v.y, 0.f);
                v.z = fmaxf(v.z, 0.f); v.w = fmaxf(v.w, 0.f);
            }
            *(float4*)(C + (size_t)r * N + c) = v;
        }
    }
}

// =====================================================================
// mma.sync bf16 2-limb / 3-term GEMM, fragment-deduplicated inner loop.
// CTA tile 128x64, K-chunk 32, double-buffered, 2 CTAs/SM.
// Decision-free GEMMs only (layer-2 expert FFN).
// =====================================================================
#define LDSM_X4(r, addr)                                                        \
    asm volatile("ldmatrix.sync.aligned.m8n8.x4.shared.b16 {%0,%1,%2,%3}, [%4];"\
        : "=r"((r)[0]), "=r"((r)[1]), "=r"((r)[2]), "=r"((r)[3]) : "r"(addr))

#define MMA_BF16(d, a, b0, b1)                                                  \
    asm volatile("mma.sync.aligned.m16n8k16.row.col.f32.bf16.bf16.f32 "         \
        "{%0,%1,%2,%3}, {%4,%5,%6,%7}, {%8,%9}, {%0,%1,%2,%3};"                 \
        : "+f"((d)[0]), "+f"((d)[1]), "+f"((d)[2]), "+f"((d)[3])                \
        : "r"((a)[0]), "r"((a)[1]), "r"((a)[2]), "r"((a)[3]), "r"(b0), "r"(b1))

#define TSTRIDE 80
#define ATILE (128 * TSTRIDE)
#define BTILE (64 * TSTRIDE)
#define BUFSZ (2 * ATILE + 2 * BTILE)
#define TA(buf, limb) ((buf) * BUFSZ + (limb) * ATILE)
#define TB(buf, limb) ((buf) * BUFSZ + 2 * ATILE + (limb) * BTILE)
#define GEMM_TC_SMEM (2 * BUFSZ)               // 61440 B -> 2 CTAs/SM

__device__ __forceinline__ void split8(const float4& f0, const float4& f1,
                                       uint32_t* ph, uint32_t* pm) {
    float v[8] = {f0.x, f0.y, f0.z, f0.w, f1.x, f1.y, f1.z, f1.w};
#pragma unroll
    for (int q = 0; q < 4; ++q) {
        float a = v[2 * q], b = v[2 * q + 1];
        __nv_bfloat162 hb = __float22bfloat162_rn(make_float2(a, b));
        ph[q] = *(uint32_t*)&hb;
        float ra = a - __bfloat162float(hb.x);
        float rb = b - __bfloat162float(hb.y);
        __nv_bfloat162 mb = __float22bfloat162_rn(make_float2(ra, rb));
        pm[q] = *(uint32_t*)&mb;
    }
}

__device__ __forceinline__ void ldgA(const float* __restrict__ src, int ldk,
                                     int k0, float4* f, int tid) {
#pragma unroll
    for (int it = 0; it < 2; ++it) {
        int G = it * 256 + tid;
        int row = G >> 2, cg = G & 3;
        const float* p = src + (size_t)row * ldk + k0 + cg * 8;
        f[it * 2 + 0] = *(const float4*)p;
        f[it * 2 + 1] = *(const float4*)(p + 4);
    }
}
__device__ __forceinline__ void stsA(const float4* f, char* __restrict__ sm,
                                     int hi_off, int mi_off, int tid) {
#pragma unroll
    for (int it = 0; it < 2; ++it) {
        int G = it * 256 + tid;
        int row = G >> 2, cg = G & 3;
        uint32_t ph[4], pm[4];
        split8(f[it * 2 + 0], f[it * 2 + 1], ph, pm);
        int off = row * TSTRIDE + cg * 16;
        *(uint4*)(sm + hi_off + off) = make_uint4(ph[0], ph[1], ph[2], ph[3]);
        *(uint4*)(sm + mi_off + off) = make_uint4(pm[0], pm[1], pm[2], pm[3]);
    }
}
__device__ __forceinline__ void ldgB(const float* __restrict__ src, int ldk,
                                     int k0, float4* f, int tid) {
    int row = tid >> 2, cg = tid & 3;
    const float* p = src + (size_t)row * ldk + k0 + cg * 8;
    f[0] = *(const float4*)p;
    f[1] = *(const float4*)(p + 4);
}
__device__ __forceinline__ void stsB(const float4* f, char* __restrict__ sm,
                                     int hi_off, int mi_off, int tid) {
    int row = tid >> 2, cg = tid & 3;
    uint32_t ph[4], pm[4];
    split8(f[0], f[1], ph, pm);
    int off = row * TSTRIDE + cg * 16;
    *(uint4*)(sm + hi_off + off) = make_uint4(ph[0], ph[1], ph[2], ph[3]);
    *(uint4*)(sm + mi_off + off) = make_uint4(pm[0], pm[1], pm[2], pm[3]);
}

template <bool RELU>
__global__ __launch_bounds__(256, 2)
void gemm_tc3(const float* __restrict__ Ag, const float* __restrict__ Bg,
              const float* __restrict__ bias, float* __restrict__ C,
              int M, int N, int Kd,
              long long aB, long long bB, long long biasB, long long cB) {
    extern __shared__ char smem[];
    uint32_t sb = smem_u32(smem);
    int tid = threadIdx.x;
    int wid = tid >> 5, lane = tid & 31;
    int wm = wid >> 2, wn = wid & 3;

    int bz = blockIdx.z;
    int rowBase = blockIdx.y * 128;
    int colBase = blockIdx.x * 64;
    const float* A = Ag + (long long)bz * aB + (size_t)rowBase * Kd;
    const float* B = Bg + (long long)bz * bB + (size_t)colBase * Kd;
    const float* bi = bias ? (bias + (long long)bz * biasB) : nullptr;
    float* Cp = C + (long long)bz * cB;

    float acc[4][2][4];
#pragma unroll
    for (int i = 0; i < 4; i++)
#pragma unroll
        for (int j = 0; j < 2; j++)
#pragma unroll
            for (int q = 0; q < 4; q++) acc[i][j][q] = 0.f;

    int lrow = lane & 15;
    int lhalf = (lane >> 4) * 8;

    float4 fa[4], fb[2];

    ldgA(A, Kd, 0, fa, tid);
    ldgB(B, Kd, 0, fb, tid);
    stsA(fa, smem, TA(0, 0), TA(0, 1), tid);
    stsB(fb, smem, TB(0, 0), TB(0, 1), tid);
    __syncthreads();

    const int nCh = Kd >> 5;
    for (int ch = 0; ch < nCh; ++ch) {
        int cur = ch & 1;
        if (ch + 1 < nCh) {
            int k0 = (ch + 1) * 32;
            ldgA(A, Kd, k0, fa, tid);
            ldgB(B, Kd, k0, fb, tid);
        }
        uint32_t aHi = sb + TA(cur, 0), aMi = sb + TA(cur, 1);
        uint32_t bHi = sb + TB(cur, 0), bMi = sb + TB(cur, 1);
#pragma unroll
        for (int ks = 0; ks < 2; ++ks) {
            uint32_t af[4][4], bfh[4], bfm[4];
            int kcol = (ks * 16 + lhalf) * 2;
            LDSM_X4(bfh, bHi + (wn * 16 + lrow) * TSTRIDE + kcol);
            LDSM_X4(bfm, bMi + (wn * 16 + lrow) * TSTRIDE + kcol);
#pragma unroll
            for (int i = 0; i < 4; ++i)
                LDSM_X4(af[i], aHi + (wm * 64 + i * 16 + lrow) * TSTRIDE + kcol);
#pragma unroll
            for (int i = 0; i < 4; ++i)
#pragma unroll
                for (int j = 0; j < 2; ++j)
                    MMA_BF16(acc[i][j], af[i], bfh[j], bfh[j + 2]);   // hh
#pragma unroll
            for (int i = 0; i < 4; ++i)
#pragma unroll
                for (int j = 0; j < 2; ++j)
                    MMA_BF16(acc[i][j], af[i], bfm[j], bfm[j + 2]);   // hm
#pragma unroll
            for (int i = 0; i < 4; ++i)
                LDSM_X4(af[i], aMi + (wm * 64 + i * 16 + lrow) * TSTRIDE + kcol);
#pragma unroll
            for (int i = 0; i < 4; ++i)
#pragma unroll
                for (int j = 0; j < 2; ++j)
                    MMA_BF16(acc[i][j], af[i], bfh[j], bfh[j + 2]);   // mh
        }
        if (ch + 1 < nCh) {
            int nxt = cur ^ 1;
            stsA(fa, smem, TA(nxt, 0), TA(nxt, 1), tid);
            stsB(fb, smem, TB(nxt, 0), TB(nxt, 1), tid);
            __syncthreads();
        }
    }

#pragma unroll
    for (int i = 0; i < 4; ++i) {
        int r0 = rowBase + wm * 64 + i * 16 + (lane >> 2);
#pragma unroll
        for (int j = 0; j < 2; ++j) {
            int c = colBase + wn * 16 + j * 8 + (lane & 3) * 2;
            float2 v0 = make_float2(acc[i][j][0], acc[i][j][1]);
            float2 v1 = make_float2(acc[i][j][2], acc[i][j][3]);
            if (bi) {
                float2 bv = *(const float2*)(bi + c);
                v0.x += bv.x; v0.y += bv.y;
                v1.x += bv.x; v1.y += bv.y;
            }
            if (RELU) {
                v0.x = fmaxf(v0.x, 0.f); v0.y = fmaxf(v0.y, 0.f);
                v1.x = fmaxf(v1.x, 0.f); v1.y = fmaxf(v1.y, 0.f);
            }
            *(float2*)(Cp + (size_t)r0 * N + c)       = v0;
            *(float2*)(Cp + (size_t)(r0 + 8) * N + c) = v1;
        }
    }
}

// ---------------- LN body shared by fused kernels ----------------
__device__ __forceinline__ void ln_body(float4 v, const float* __restrict__ w,
                                        const float* __restrict__ b,
                                        float* __restrict__ out, int t, int j) {
    float s = v.x + v.y + v.z + v.w;
    float q = v.x * v.x + v.y * v.y + v.z * v.z + v.w * v.w;
#pragma unroll
    for (int o = 16; o > 0; o >>= 1) {
        s += __shfl_xor_sync(0xffffffffu, s, o);
        q += __shfl_xor_sync(0xffffffffu, q, o);
    }
    __shared__ float ss[8], sq[8];
    if ((j & 31) == 0) { ss[j >> 5] = s; sq[j >> 5] = q; }
    __syncthreads();
    float S = 0.f, Q = 0.f;
#pragma unroll
    for (int k = 0; k < 8; k++) { S += ss[k]; Q += sq[k]; }
    float mean = S * (1.f / DD);
    float var  = Q * (1.f / DD) - mean * mean;
    float rstd = rsqrtf(var + 1e-5f);
    float4 wv = ((const float4*)w)[j];
    float4 bv = ((const float4*)b)[j];
    float4 o4;
    o4.x = (v.x - mean) * rstd * wv.x + bv.x;
    o4.y = (v.y - mean) * rstd * wv.y + bv.y;
    o4.z = (v.z - mean) * rstd * wv.z + bv.z;
    o4.w = (v.w - mean) * rstd * wv.w + bv.w;
    ((float4*)(out + (size_t)t * DD))[j] = o4;
}

// ---------------- fused embedding + ln1 ----------------
__global__ void embed_ln_kernel(const int* __restrict__ ids,
                                const float* __restrict__ tok,
                                const float* __restrict__ pe,
                                const float* __restrict__ w,
                                const float* __restrict__ b,
                                float* __restrict__ x,
                                float* __restrict__ xn) {
    int t = blockIdx.x, j = threadIdx.x;
    int id = ids[t];
    float4 a = ((const float4*)(tok + (size_t)id * DD))[j];
    float4 p = ((const float4*)(pe  + (size_t)t  * DD))[j];
    a.x += p.x; a.y += p.y; a.z += p.z; a.w += p.w;
    ((float4*)(x + (size_t)t * DD))[j] = a;
    ln_body(a, w, b, xn, t, j);
}

// ---------------- standalone layernorm (for ln2) ----------------
__global__ void ln_kernel(const float* __restrict__ x,
                          const float* __restrict__ w,
                          const float* __restrict__ b,
                          float* __restrict__ out) {
    int t = blockIdx.x, j = threadIdx.x;
    float4 v = ((const float4*)(x + (size_t)t * DD))[j];
    ln_body(v, w, b, out, t, j);
}

// ---------------- fused combine + next LN ----------------
__global__ void combine_ln_kernel(float* __restrict__ x,
                                  const float* __restrict__ eo,
                                  const int* __restrict__ pos,
                                  const float* __restrict__ gate,
                                  const float* __restrict__ w,
                                  const float* __restrict__ b,
                                  float* __restrict__ out) {
    int t = blockIdx.x, j = threadIdx.x;
    int p0 = pos[2 * t], p1 = pos[2 * t + 1];
    float g0 = gate[2 * t], g1 = gate[2 * t + 1];
    float4 v = ((const float4*)(x + (size_t)t * DD))[j];
    if (p0 >= 0) {
        float4 a = ((const float4*)(eo + (size_t)p0 * DD))[j];
        v.x += g0 * a.x; v.y += g0 * a.y; v.z += g0 * a.z; v.w += g0 * a.w;
    }
    if (p1 >= 0) {
        float4 a = ((const float4*)(eo + (size_t)p1 * DD))[j];
        v.x += g1 * a.x; v.y += g1 * a.y; v.z += g1 * a.z; v.w += g1 * a.w;
    }
    ((float4*)(x + (size_t)t * DD))[j] = v;
    ln_body(v, w, b, out, t, j);
}

// ---------------- RoPE in-place on q,k; 8 warps per block ----------------
__global__ __launch_bounds__(256)
void rope_kernel(float* __restrict__ qkv) {
    int gw = blockIdx.x * 8 + (threadIdx.x >> 5);
    int t = gw >> 4, h = gw & 15;
    int i = threadIdx.x & 31;
    float div = expf((float)(-2 * i) * (logf(10000.f) / 64.f));
    float ang = (float)t * div;
    float s, c;
    sincosf(ang, &s, &c);
#pragma unroll
    for (int which = 0; which < 2; which++) {
        float* b = qkv + (size_t)t * (3 * DD) + which * DD + h * HS;
        float t1 = b[i], t2 = b[i + 32];
        b[i]      = t1 * c - t2 * s;
        b[i + 32] = t2 * c + t1 * s;
    }
}

// ---------------- flash attention; output (H, T, HS) "bhtd" ----------------
// 64 queries / 64 threads per block; K/V tiles cp.async double-buffered
// (dynamic smem 64KB). Values and per-thread math identical -> bitwise-same.
#define AKV(buf, kv, s, c) (((buf) * 2048 + (kv) * 1024 + (s) * 16 + (c)) * 16)

__global__ __launch_bounds__(64)
void attn_kernel(const float* __restrict__ qkv, float* __restrict__ av) {
    extern __shared__ float4 sKV[];
    uint32_t sb = smem_u32(sKV);
    int h = blockIdx.y;
    int qtile = gridDim.x - 1 - blockIdx.x;   // heavy workloads first
    int qt = qtile * 64 + threadIdx.x;
    int tid = threadIdx.x;

    float4 qv[16];
    const float4* qrow = (const float4*)(qkv + (size_t)qt * (3 * DD) + h * HS);
#pragma unroll
    for (int i = 0; i < 16; i++) qv[i] = qrow[i];

    ull o2[32];
#pragma unroll
    for (int d = 0; d < 32; d++) o2[d] = 0ULL;
    float m = -1e30f, l = 0.f;

    int nkt = qtile + 1;

    // prologue: issue tile 0 into buffer 0
#pragma unroll
    for (int j = 0; j < 16; j++) {
        int idx = tid + j * 64;
        int s = idx >> 4, c = idx & 15;
        const float* base = qkv + (size_t)s * (3 * DD) + h * HS + c * 4;
        CP_ASYNC16(sb + AKV(0, 0, s, c), base + DD);
        CP_ASYNC16(sb + AKV(0, 1, s, c), base + 2 * DD);
    }
    CP_COMMIT();

    for (int kt = 0; kt < nkt; kt++) {
        int buf = kt & 1;
        __syncthreads();   // all warps done computing on buf^1 (prev iter)
        if (kt + 1 < nkt) {
#pragma unroll
            for (int j = 0; j < 16; j++) {
                int idx = tid + j * 64;
                int s = idx >> 4, c = idx & 15;
                const float* base = qkv + (size_t)((kt + 1) * 64 + s) * (3 * DD)
                                  + h * HS + c * 4;
                CP_ASYNC16(sb + AKV(buf ^ 1, 0, s, c), base + DD);
                CP_ASYNC16(sb + AKV(buf ^ 1, 1, s, c), base + 2 * DD);
            }
            CP_COMMIT();
            CP_WAIT(1);    // oldest group (tile kt) complete
        } else {
            CP_WAIT(0);
        }
        __syncthreads();   // tile kt visible to all warps

        const float4* Ks = sKV + buf * 2048;
        const float4* Vs = sKV + buf * 2048 + 1024;

#pragma unroll
        for (int sub = 0; sub < 4; sub++) {
            float sc[16];
            float tmax = -1e30f;
#pragma unroll
            for (int s = 0; s < 16; s++) {
                int ls = sub * 16 + s;
                float acc = 0.f;
#pragma unroll
                for (int i = 0; i < 16; i++) {
                    float4 k4 = Ks[ls * 16 + i];
                    acc += qv[i].x * k4.x + qv[i].y * k4.y + qv[i].z * k4.z + qv[i].w * k4.w;
                }
                int gs = kt * 64 + ls;
                acc = (gs <= qt) ? acc * 0.125f : -1e30f;
                sc[s] = acc;
                tmax = fmaxf(tmax, acc);
            }
            float nm = fmaxf(m, tmax);
            float scale = __expf(m - nm);
            l *= scale;
            ull s2 = pack2(scale, scale);
#pragma unroll
            for (int d = 0; d < 32; d++) mul2(o2[d], s2);
#pragma unroll
            for (int s = 0; s < 16; s++) {
                int ls = sub * 16 + s;
                float p = __expf(sc[s] - nm);
                l += p;
                ull p2 = pack2(p, p);
                const ulonglong2* vrow = (const ulonglong2*)&Vs[ls * 16];
#pragma unroll
                for (int i = 0; i < 16; i++) {
                    ulonglong2 vv = vrow[i];
                    fma2(o2[i * 2 + 0], p2, vv.x);
                    fma2(o2[i * 2 + 1], p2, vv.y);
                }
            }
            m = nm;
        }
    }
    float inv = 1.f / l;
    float* orow = av + ((size_t)h * TT + qt) * HS;
#pragma unroll
    for (int i = 0; i < 16; i++) {
        float4 v;
        float e0, e1, e2, e3;
        unpack2(o2[i * 2 + 0], e0, e1);
        unpack2(o2[i * 2 + 1], e2, e3);
        v.x = e0 * inv; v.y = e1 * inv;
        v.z = e2 * inv; v.w = e3 * inv;
        ((float4*)orow)[i] = v;
    }
}
#define ATTN_SMEM (4096 * 16)   // 65536 B

// ---------------- router: logits, noisy top-2, gates ----------------
__global__ void router_kernel(const float* __restrict__ xn,
                              const float* __restrict__ rw, const float* __restrict__ rb,
                              const float* __restrict__ nw, const float* __restrict__ nb,
                              const float* __restrict__ noise,
                              int* __restrict__ topi, float* __restrict__ gate) {
    int t = blockIdx.x;
    int wid = threadIdx.x >> 5, lane = threadIdx.x & 31;
    __shared__ float noisy[EE];
    const float4* x4 = (const float4*)(xn + (size_t)t * DD);
    const float4* r4 = (const float4*)(rw + (size_t)wid * DD);
    const float4* n4 = (const float4*)(nw + (size_t)wid * DD);
    float a = 0.f, c = 0.f;
    for (int j = lane; j < DD / 4; j += 32) {
        float4 xv = x4[j], rv = r4[j], nv = n4[j];
        a += xv.x * rv.x + xv.y * rv.y + xv.z * rv.z + xv.w * rv.w;
        c += xv.x * nv.x + xv.y * nv.y + xv.z * nv.z + xv.w * nv.w;
    }
#pragma unroll
    for (int o = 16; o > 0; o >>= 1) {
        a += __shfl_xor_sync(0xffffffffu, a, o);
        c += __shfl_xor_sync(0xffffffffu, c, o);
    }
    if (lane == 0) {
        float logit = a + rb[wid];
        float nl = c + nb[wid];
        float sp = (nl > 20.f) ? nl : log1pf(expf(nl));
        noisy[wid] = logit + noise[(size_t)t * EE + wid] * sp;
    }
    __syncthreads();
    if (threadIdx.x == 0) {
        int i0 = 0; float v0 = noisy[0];
#pragma unroll
        for (int e = 1; e < EE; e++) if (noisy[e] > v0) { v0 = noisy[e]; i0 = e; }
        int i1 = -1; float v1 = -1e30f;
#pragma unroll
        for (int e = 0; e < EE; e++) if (e != i0 && noisy[e] > v1) { v1 = noisy[e]; i1 = e; }
        float g0 = 1.f / (1.f + expf(v1 - v0));
        topi[t * 2] = i0; topi[t * 2 + 1] = i1;
        gate[t * 2] = g0; gate[t * 2 + 1] = 1.f - g0;
    }
}

// ---------------- capacity rank / position ----------------
__global__ void rank_kernel(const int* __restrict__ topi, int* __restrict__ pos) {
    int e = threadIdx.x >> 5, lane = threadIdx.x & 31;
    int base = 0;
    for (int c = 0; c < (TT * KK) / 32; c++) {
        int i = c * 32 + lane;
        int ef = topi[i];
        bool mt = (ef == e);
        unsigned msk = __ballot_sync(0xffffffffu, mt);
        if (mt) {
            int r = base + __popc(msk & ((1u << lane) - 1u));
            pos[i] = (r < CAP) ? (e * CAP + r) : -1;
        }
        base += __popc(msk);
    }
}

// ---------------- dispatch gather ----------------
__global__ void dispatch_kernel(const float* __restrict__ xn,
                                const int* __restrict__ pos,
                                float* __restrict__ de) {
    int i = blockIdx.x;
    int p = pos[i];
    if (p < 0) return;
    int t = i >> 1;
    ((float4*)(de + (size_t)p * DD))[threadIdx.x] =
        ((const float4*)(xn + (size_t)t * DD))[threadIdx.x];
}

// ---------------- host side ----------------
static void run_gemm_ffma(const float* A, const float* B, const float* bias,
                          const float* res, float* C, int M, int N, int Kd, int batch,
                          long long aB, long long bB, long long biasB, long long cB,
                          bool relu) {
    dim3 grid(N / 128, M / 128, batch), blk(256);
    if (res) {
        gemm_kernel<false, true><<<grid, blk>>>(A, B, bias, res, C, M, N, Kd, aB, bB, biasB, cB);
    } else if (relu) {
        gemm_kernel<true, false><<<grid, blk>>>(A, B, bias, nullptr, C, M, N, Kd, aB, bB, biasB, cB);
    } else {
        gemm_kernel<false, false><<<grid, blk>>>(A, B, bias, nullptr, C, M, N, Kd, aB, bB, biasB, cB);
    }
}

static void run_gemm_tc(const float* A, const float* B, const float* bias,
                        float* C, int M, int N, int Kd, int batch,
                        long long aB, long long bB, long long biasB, long long cB,
                        bool relu) {
    dim3 grid(N / 64, M / 128, batch), blk(256);
    if (relu)
        gemm_tc3<true><<<grid, blk, GEMM_TC_SMEM>>>(A, B, bias, C, M, N, Kd, aB, bB, biasB, cB);
    else
        gemm_tc3<false><<<grid, blk, GEMM_TC_SMEM>>>(A, B, bias, C, M, N, Kd, aB, bB, biasB, cB);
}

extern "C" void kernel_launch(void* const* d_in, const int* in_sizes, int n_in,
                              void* d_out, int out_size) {
    const int*   ids      = (const int*)  d_in[0];
    const float* noise    = (const float*)d_in[1];
    const float* tok_emb  = (const float*)d_in[2];
    const float* pos_emb  = (const float*)d_in[3];
    const float* ln1_w    = (const float*)d_in[4];
    const float* ln1_b    = (const float*)d_in[5];
    const float* ln2_w    = (const float*)d_in[6];
    const float* ln2_b    = (const float*)d_in[7];
    const float* qkv_w    = (const float*)d_in[8];
    const float* out_w    = (const float*)d_in[9];
    const float* router_w = (const float*)d_in[10];
    const float* router_b = (const float*)d_in[11];
    const float* noise_w  = (const float*)d_in[12];
    const float* noise_b  = (const float*)d_in[13];
    const float* e_w1     = (const float*)d_in[14];
    const float* e_b1     = (const float*)d_in[15];
    const float* e_w2     = (const float*)d_in[16];
    const float* e_b2     = (const float*)d_in[17];
    const float* lnf_w    = (const float*)d_in[18];
    const float* lnf_b    = (const float*)d_in[19];

    static bool attr_set = false;
    if (!attr_set) {
        cudaFuncSetAttribute(gemm_tc3<true>,  cudaFuncAttributeMaxDynamicSharedMemorySize, GEMM_TC_SMEM);
        cudaFuncSetAttribute(gemm_tc3<false>, cudaFuncAttributeMaxDynamicSharedMemorySize, GEMM_TC_SMEM);
        cudaFuncSetAttribute(attn_kernel,     cudaFuncAttributeMaxDynamicSharedMemorySize, ATTN_SMEM);
        attr_set = true;
    }

    float *x, *xn, *qkv, *av, *de, *h, *eo, *gate;
    int *topi, *pos;
    cudaGetSymbolAddress((void**)&x,    g_x);
    cudaGetSymbolAddress((void**)&xn,   g_xn);
    cudaGetSymbolAddress((void**)&qkv,  g_qkv);
    cudaGetSymbolAddress((void**)&av,   g_av);
    cudaGetSymbolAddress((void**)&de,   g_de);
    cudaGetSymbolAddress((void**)&h,    g_h);
    cudaGetSymbolAddress((void**)&eo,   g_eo);
    cudaGetSymbolAddress((void**)&topi, g_topi);
    cudaGetSymbolAddress((void**)&pos,  g_pos);
    cudaGetSymbolAddress((void**)&gate, g_gate);

    // embed + ln1(layer 0) fused
    embed_ln_kernel<<<TT, 256>>>(ids, tok_emb, pos_emb, ln1_w, ln1_b, x, xn);

    for (int l = 0; l < LL; l++) {
        bool fast_experts = (l == LL - 1);   // post-all-routers -> MMA safe

        // attention block (router-sensitive: bitwise FFMA path); xn = ln1(x)
        run_gemm_ffma(xn, qkv_w + (size_t)l * 3 * DD * DD, nullptr, nullptr, qkv,
                      TT, 3 * DD, DD, 1, 0, 0, 0, 0, false);
        rope_kernel<<<TT * HH / 8, 256>>>(qkv);
        attn_kernel<<<dim3(TT / 64, HH), 64, ATTN_SMEM>>>(qkv, av);
        run_gemm_ffma(av, out_w + (size_t)l * DD * DD, nullptr, x, x,
                      TT, DD, DD, 1, 0, 0, 0, 0, false);

        // MoE block
        ln_kernel<<<TT, 256>>>(x, ln2_w + (size_t)l * DD, ln2_b + (size_t)l * DD, xn);
        router_kernel<<<TT, 256>>>(xn,
                                   router_w + (size_t)l * EE * DD, router_b + (size_t)l * EE,
                                   noise_w  + (size_t)l * EE * DD, noise_b  + (size_t)l * EE,
                                   noise + (size_t)l * TT * EE, topi, gate);
        rank_kernel<<<1, 256>>>(topi, pos);
        dispatch_kernel<<<TT * KK, 256>>>(xn, pos, de);
        if (fast_experts) {
            run_gemm_tc(de, e_w1 + (size_t)l * EE * FF * DD, e_b1 + (size_t)l * EE * FF,
                        h, CAP, FF, DD, EE,
                        (long long)CAP * DD, (long long)FF * DD, FF, (long long)CAP * FF, true);
            run_gemm_tc(h, e_w2 + (size_t)l * EE * DD * FF, e_b2 + (size_t)l * EE * DD,
                        eo, CAP, DD, FF, EE,
                        (long long)CAP * FF, (long long)DD * FF, DD, (long long)CAP * DD, false);
        } else {
            run_gemm_ffma(de, e_w1 + (size_t)l * EE * FF * DD, e_b1 + (size_t)l * EE * FF,
                          nullptr, h, CAP, FF, DD, EE,
                          (long long)CAP * DD, (long long)FF * DD, FF, (long long)CAP * FF, true);
            run_gemm_ffma(h, e_w2 + (size_t)l * EE * DD * FF, e_b2 + (size_t)l * EE * DD,
                          nullptr, eo, CAP, DD, FF, EE,
                          (long long)CAP * FF, (long long)DD * FF, DD, (long long)CAP * DD, false);
        }
        // combine + next LN fused (ln1 of next layer, or final lnf -> d_out)
        if (l + 1 < LL) {
            combine_ln_kernel<<<TT, 256>>>(x, eo, pos, gate,
                                           ln1_w + (size_t)(l + 1) * DD,
                                           ln1_b + (size_t)(l + 1) * DD, xn);
        } else {
            combine_ln_kernel<<<TT, 256>>>(x, eo, pos, gate,
                                           lnf_w, lnf_b, (float*)d_out);
        }
    }
}

// round 16
// speedup vs baseline: 1.0238x; 1.0238x over previous
#include <cuda_runtime.h>
#include <cuda_bf16.h>
#include <cstdint>
#include <math.h>

// ---------------- constants ----------------
#define TT   2048
#define DD   1024
#define HH   16
#define HS   64
#define EE   8
#define KK   2
#define LL   2
#define CAP  512
#define FF   4096   // 4*D

// ---------------- scratch (device globals; no allocation allowed) ----------
__device__ float g_x  [TT * DD];
__device__ float g_xn [TT * DD];
__device__ float g_qkv[TT * 3 * DD];
__device__ float g_av [TT * DD];
__device__ float g_de [EE * CAP * DD];
__device__ float g_h  [EE * CAP * FF];
__device__ float g_eo [EE * CAP * DD];
__device__ int   g_topi[TT * KK];
__device__ int   g_pos [TT * KK];
__device__ float g_gate[TT * KK];

// ---------------- packed f32x2 helpers ----------------
typedef unsigned long long ull;
__device__ __forceinline__ ull pack2(float lo, float hi) {
    ull r;
    asm("mov.b64 %0, {%1, %2};" : "=l"(r) : "f"(lo), "f"(hi));
    return r;
}
__device__ __forceinline__ void unpack2(ull v, float& lo, float& hi) {
    asm("mov.b64 {%0, %1}, %2;" : "=f"(lo), "=f"(hi) : "l"(v));
}
__device__ __forceinline__ void fma2(ull& d, ull a, ull b) {
    asm("fma.rn.f32x2 %0, %1, %2, %0;" : "+l"(d) : "l"(a), "l"(b));
}
__device__ __forceinline__ void mul2(ull& d, ull a) {
    asm("mul.rn.f32x2 %0, %0, %1;" : "+l"(d) : "l"(a));
}

__device__ __forceinline__ uint32_t smem_u32(const void* p) {
    uint32_t a;
    asm("{ .reg .u64 t; cvta.to.shared.u64 t, %1; cvt.u32.u64 %0, t; }" : "=r"(a) : "l"(p));
    return a;
}

// =====================================================================
// fp32 GEMM, packed f32x2 FMA, double-buffered (bitwise == round 3 ->
// router decisions preserved). C = A(MxK)*B(NxK)^T (+bias)(+res)(relu).
// =====================================================================
template <bool RELU, bool RES>
__global__ __launch_bounds__(256)
void gemm_kernel(const float* __restrict__ A, const float* __restrict__ Bm,
                 const float* __restrict__ bias, const float* res,
                 float* C,
                 int M, int N, int Kd,
                 long long aB, long long bB, long long biasB, long long cB) {
    int bz = blockIdx.z;
    A  += (long long)bz * aB;
    Bm += (long long)bz * bB;
    C  += (long long)bz * cB;
    if (bias) bias += (long long)bz * biasB;

    int rowBase = blockIdx.y * 128;
    int colBase = blockIdx.x * 128;

    __shared__ float As[2][16][128];
    __shared__ float Bs[2][16][128];

    int tid = threadIdx.x;
    int tx = tid & 15, ty = tid >> 4;
    int lrow = tid >> 2;
    int lcol = (tid & 3) * 4;

    const float* Arow0 = A  + (size_t)(rowBase + lrow)      * Kd + lcol;
    const float* Arow1 = A  + (size_t)(rowBase + lrow + 64) * Kd + lcol;
    const float* Brow0 = Bm + (size_t)(colBase + lrow)      * Kd + lcol;
    const float* Brow1 = Bm + (size_t)(colBase + lrow + 64) * Kd + lcol;

    ull acc2[8][4];
#pragma unroll
    for (int i = 0; i < 8; i++)
#pragma unroll
        for (int j = 0; j < 4; j++) acc2[i][j] = 0ULL;

    float4 ra0, ra1, rb0, rb1;

    ra0 = *(const float4*)(Arow0);
    ra1 = *(const float4*)(Arow1);
    rb0 = *(const float4*)(Brow0);
    rb1 = *(const float4*)(Brow1);
    {
        float* a0 = &As[0][lcol][lrow];
        a0[0 * 128] = ra0.x; a0[1 * 128] = ra0.y; a0[2 * 128] = ra0.z; a0[3 * 128] = ra0.w;
        float* a1 = &As[0][lcol][lrow + 64];
        a1[0 * 128] = ra1.x; a1[1 * 128] = ra1.y; a1[2 * 128] = ra1.z; a1[3 * 128] = ra1.w;
        float* b0 = &Bs[0][lcol][lrow];
        b0[0 * 128] = rb0.x; b0[1 * 128] = rb0.y; b0[2 * 128] = rb0.z; b0[3 * 128] = rb0.w;
        float* b1 = &Bs[0][lcol][lrow + 64];
        b1[0 * 128] = rb1.x; b1[1 * 128] = rb1.y; b1[2 * 128] = rb1.z; b1[3 * 128] = rb1.w;
    }
    __syncthreads();

    const int nCh = Kd >> 4;
    for (int ch = 0; ch < nCh; ++ch) {
        int cur = ch & 1;
        if (ch + 1 < nCh) {
            int k0 = (ch + 1) << 4;
            ra0 = *(const float4*)(Arow0 + k0);
            ra1 = *(const float4*)(Arow1 + k0);
            rb0 = *(const float4*)(Brow0 + k0);
            rb1 = *(const float4*)(Brow1 + k0);
        }
#pragma unroll
        for (int kk = 0; kk < 16; kk++) {
            float4 a0 = *(const float4*)&As[cur][kk][ty * 4];
            float4 a1 = *(const float4*)&As[cur][kk][64 + ty * 4];
            ulonglong2 bb0 = *(const ulonglong2*)&Bs[cur][kk][tx * 4];
            ulonglong2 bb1 = *(const ulonglong2*)&Bs[cur][kk][64 + tx * 4];
            float ar[8] = {a0.x, a0.y, a0.z, a0.w, a1.x, a1.y, a1.z, a1.w};
            ull b2[4] = {bb0.x, bb0.y, bb1.x, bb1.y};
#pragma unroll
            for (int i = 0; i < 8; i++) {
                ull a2 = pack2(ar[i], ar[i]);
#pragma unroll
                for (int j = 0; j < 4; j++) fma2(acc2[i][j], a2, b2[j]);
            }
        }
        if (ch + 1 < nCh) {
            int nxt = cur ^ 1;
            float* a0 = &As[nxt][lcol][lrow];
            a0[0 * 128] = ra0.x; a0[1 * 128] = ra0.y; a0[2 * 128] = ra0.z; a0[3 * 128] = ra0.w;
            float* a1 = &As[nxt][lcol][lrow + 64];
            a1[0 * 128] = ra1.x; a1[1 * 128] = ra1.y; a1[2 * 128] = ra1.z; a1[3 * 128] = ra1.w;
            float* b0 = &Bs[nxt][lcol][lrow];
            b0[0 * 128] = rb0.x; b0[1 * 128] = rb0.y; b0[2 * 128] = rb0.z; b0[3 * 128] = rb0.w;
            float* b1 = &Bs[nxt][lcol][lrow + 64];
            b1[0 * 128] = rb1.x; b1[1 * 128] = rb1.y; b1[2 * 128] = rb1.z; b1[3 * 128] = rb1.w;
            __syncthreads();
        }
    }

#pragma unroll
    for (int i = 0; i < 8; i++) {
        int r = rowBase + ((i < 4) ? (ty * 4 + i) : (64 + ty * 4 + (i - 4)));
#pragma unroll
        for (int jj = 0; jj < 2; jj++) {
            int c = colBase + jj * 64 + tx * 4;
            float4 v;
            unpack2(acc2[i][jj * 2 + 0], v.x, v.y);
            unpack2(acc2[i][jj * 2 + 1], v.z, v.w);
            if (bias) {
                v.x += bias[c]; v.y += bias[c + 1];
                v.z += bias[c + 2]; v.w += bias[c + 3];
            }
            if (RES) {
                float4 rv = *(const float4*)(res + (size_t)r * N + c);
                v.x = rv.x + v.x; v.y = rv.y + v.y;
                v.z = rv.z + v.z; v.w = rv.w + v.w;
            }
            if (RELU) {
                v.x = fmaxf(v.x, 0.f); v.y = fmaxf(v.y, 0.f);
                v.z = fmaxf(v.z, 0.f); v.w = fmaxf(v.w, 0.f);
            }
            *(float4*)(C + (size_t)r * N + c) = v;
        }
    }
}

// =====================================================================
// mma.sync bf16 2-limb / 3-term GEMM, fragment-deduplicated inner loop.
// CTA tile 128x64, K-chunk 32, double-buffered, 2 CTAs/SM.
// Decision-free GEMMs only (layer-2 expert FFN).
// =====================================================================
#define LDSM_X4(r, addr)                                                        \
    asm volatile("ldmatrix.sync.aligned.m8n8.x4.shared.b16 {%0,%1,%2,%3}, [%4];"\
        : "=r"((r)[0]), "=r"((r)[1]), "=r"((r)[2]), "=r"((r)[3]) : "r"(addr))

#define MMA_BF16(d, a, b0, b1)                                                  \
    asm volatile("mma.sync.aligned.m16n8k16.row.col.f32.bf16.bf16.f32 "         \
        "{%0,%1,%2,%3}, {%4,%5,%6,%7}, {%8,%9}, {%0,%1,%2,%3};"                 \
        : "+f"((d)[0]), "+f"((d)[1]), "+f"((d)[2]), "+f"((d)[3])                \
        : "r"((a)[0]), "r"((a)[1]), "r"((a)[2]), "r"((a)[3]), "r"(b0), "r"(b1))

#define TSTRIDE 80
#define ATILE (128 * TSTRIDE)
#define BTILE (64 * TSTRIDE)
#define BUFSZ (2 * ATILE + 2 * BTILE)
#define TA(buf, limb) ((buf) * BUFSZ + (limb) * ATILE)
#define TB(buf, limb) ((buf) * BUFSZ + 2 * ATILE + (limb) * BTILE)
#define GEMM_TC_SMEM (2 * BUFSZ)               // 61440 B -> 2 CTAs/SM

__device__ __forceinline__ void split8(const float4& f0, const float4& f1,
                                       uint32_t* ph, uint32_t* pm) {
    float v[8] = {f0.x, f0.y, f0.z, f0.w, f1.x, f1.y, f1.z, f1.w};
#pragma unroll
    for (int q = 0; q < 4; ++q) {
        float a = v[2 * q], b = v[2 * q + 1];
        __nv_bfloat162 hb = __float22bfloat162_rn(make_float2(a, b));
        ph[q] = *(uint32_t*)&hb;
        float ra = a - __bfloat162float(hb.x);
        float rb = b - __bfloat162float(hb.y);
        __nv_bfloat162 mb = __float22bfloat162_rn(make_float2(ra, rb));
        pm[q] = *(uint32_t*)&mb;
    }
}

__device__ __forceinline__ void ldgA(const float* __restrict__ src, int ldk,
                                     int k0, float4* f, int tid) {
#pragma unroll
    for (int it = 0; it < 2; ++it) {
        int G = it * 256 + tid;
        int row = G >> 2, cg = G & 3;
        const float* p = src + (size_t)row * ldk + k0 + cg * 8;
        f[it * 2 + 0] = *(const float4*)p;
        f[it * 2 + 1] = *(const float4*)(p + 4);
    }
}
__device__ __forceinline__ void stsA(const float4* f, char* __restrict__ sm,
                                     int hi_off, int mi_off, int tid) {
#pragma unroll
    for (int it = 0; it < 2; ++it) {
        int G = it * 256 + tid;
        int row = G >> 2, cg = G & 3;
        uint32_t ph[4], pm[4];
        split8(f[it * 2 + 0], f[it * 2 + 1], ph, pm);
        int off = row * TSTRIDE + cg * 16;
        *(uint4*)(sm + hi_off + off) = make_uint4(ph[0], ph[1], ph[2], ph[3]);
        *(uint4*)(sm + mi_off + off) = make_uint4(pm[0], pm[1], pm[2], pm[3]);
    }
}
__device__ __forceinline__ void ldgB(const float* __restrict__ src, int ldk,
                                     int k0, float4* f, int tid) {
    int row = tid >> 2, cg = tid & 3;
    const float* p = src + (size_t)row * ldk + k0 + cg * 8;
    f[0] = *(const float4*)p;
    f[1] = *(const float4*)(p + 4);
}
__device__ __forceinline__ void stsB(const float4* f, char* __restrict__ sm,
                                     int hi_off, int mi_off, int tid) {
    int row = tid >> 2, cg = tid & 3;
    uint32_t ph[4], pm[4];
    split8(f[0], f[1], ph, pm);
    int off = row * TSTRIDE + cg * 16;
    *(uint4*)(sm + hi_off + off) = make_uint4(ph[0], ph[1], ph[2], ph[3]);
    *(uint4*)(sm + mi_off + off) = make_uint4(pm[0], pm[1], pm[2], pm[3]);
}

template <bool RELU>
__global__ __launch_bounds__(256, 2)
void gemm_tc3(const float* __restrict__ Ag, const float* __restrict__ Bg,
              const float* __restrict__ bias, float* __restrict__ C,
              int M, int N, int Kd,
              long long aB, long long bB, long long biasB, long long cB) {
    extern __shared__ char smem[];
    uint32_t sb = smem_u32(smem);
    int tid = threadIdx.x;
    int wid = tid >> 5, lane = tid & 31;
    int wm = wid >> 2, wn = wid & 3;

    int bz = blockIdx.z;
    int rowBase = blockIdx.y * 128;
    int colBase = blockIdx.x * 64;
    const float* A = Ag + (long long)bz * aB + (size_t)rowBase * Kd;
    const float* B = Bg + (long long)bz * bB + (size_t)colBase * Kd;
    const float* bi = bias ? (bias + (long long)bz * biasB) : nullptr;
    float* Cp = C + (long long)bz * cB;

    float acc[4][2][4];
#pragma unroll
    for (int i = 0; i < 4; i++)
#pragma unroll
        for (int j = 0; j < 2; j++)
#pragma unroll
            for (int q = 0; q < 4; q++) acc[i][j][q] = 0.f;

    int lrow = lane & 15;
    int lhalf = (lane >> 4) * 8;

    float4 fa[4], fb[2];

    ldgA(A, Kd, 0, fa, tid);
    ldgB(B, Kd, 0, fb, tid);
    stsA(fa, smem, TA(0, 0), TA(0, 1), tid);
    stsB(fb, smem, TB(0, 0), TB(0, 1), tid);
    __syncthreads();

    const int nCh = Kd >> 5;
    for (int ch = 0; ch < nCh; ++ch) {
        int cur = ch & 1;
        if (ch + 1 < nCh) {
            int k0 = (ch + 1) * 32;
            ldgA(A, Kd, k0, fa, tid);
            ldgB(B, Kd, k0, fb, tid);
        }
        uint32_t aHi = sb + TA(cur, 0), aMi = sb + TA(cur, 1);
        uint32_t bHi = sb + TB(cur, 0), bMi = sb + TB(cur, 1);
#pragma unroll
        for (int ks = 0; ks < 2; ++ks) {
            uint32_t af[4][4], bfh[4], bfm[4];
            int kcol = (ks * 16 + lhalf) * 2;
            LDSM_X4(bfh, bHi + (wn * 16 + lrow) * TSTRIDE + kcol);
            LDSM_X4(bfm, bMi + (wn * 16 + lrow) * TSTRIDE + kcol);
#pragma unroll
            for (int i = 0; i < 4; ++i)
                LDSM_X4(af[i], aHi + (wm * 64 + i * 16 + lrow) * TSTRIDE + kcol);
#pragma unroll
            for (int i = 0; i < 4; ++i)
#pragma unroll
                for (int j = 0; j < 2; ++j)
                    MMA_BF16(acc[i][j], af[i], bfh[j], bfh[j + 2]);   // hh
#pragma unroll
            for (int i = 0; i < 4; ++i)
#pragma unroll
                for (int j = 0; j < 2; ++j)
                    MMA_BF16(acc[i][j], af[i], bfm[j], bfm[j + 2]);   // hm
#pragma unroll
            for (int i = 0; i < 4; ++i)
                LDSM_X4(af[i], aMi + (wm * 64 + i * 16 + lrow) * TSTRIDE + kcol);
#pragma unroll
            for (int i = 0; i < 4; ++i)
#pragma unroll
                for (int j = 0; j < 2; ++j)
                    MMA_BF16(acc[i][j], af[i], bfh[j], bfh[j + 2]);   // mh
        }
        if (ch + 1 < nCh) {
            int nxt = cur ^ 1;
            stsA(fa, smem, TA(nxt, 0), TA(nxt, 1), tid);
            stsB(fb, smem, TB(nxt, 0), TB(nxt, 1), tid);
            __syncthreads();
        }
    }

#pragma unroll
    for (int i = 0; i < 4; ++i) {
        int r0 = rowBase + wm * 64 + i * 16 + (lane >> 2);
#pragma unroll
        for (int j = 0; j < 2; ++j) {
            int c = colBase + wn * 16 + j * 8 + (lane & 3) * 2;
            float2 v0 = make_float2(acc[i][j][0], acc[i][j][1]);
            float2 v1 = make_float2(acc[i][j][2], acc[i][j][3]);
            if (bi) {
                float2 bv = *(const float2*)(bi + c);
                v0.x += bv.x; v0.y += bv.y;
                v1.x += bv.x; v1.y += bv.y;
            }
            if (RELU) {
                v0.x = fmaxf(v0.x, 0.f); v0.y = fmaxf(v0.y, 0.f);
                v1.x = fmaxf(v1.x, 0.f); v1.y = fmaxf(v1.y, 0.f);
            }
            *(float2*)(Cp + (size_t)r0 * N + c)       = v0;
            *(float2*)(Cp + (size_t)(r0 + 8) * N + c) = v1;
        }
    }
}

// ---------------- LN body shared by fused kernels ----------------
__device__ __forceinline__ void ln_body(float4 v, const float* __restrict__ w,
                                        const float* __restrict__ b,
                                        float* __restrict__ out, int t, int j) {
    float s = v.x + v.y + v.z + v.w;
    float q = v.x * v.x + v.y * v.y + v.z * v.z + v.w * v.w;
#pragma unroll
    for (int o = 16; o > 0; o >>= 1) {
        s += __shfl_xor_sync(0xffffffffu, s, o);
        q += __shfl_xor_sync(0xffffffffu, q, o);
    }
    __shared__ float ss[8], sq[8];
    if ((j & 31) == 0) { ss[j >> 5] = s; sq[j >> 5] = q; }
    __syncthreads();
    float S = 0.f, Q = 0.f;
#pragma unroll
    for (int k = 0; k < 8; k++) { S += ss[k]; Q += sq[k]; }
    float mean = S * (1.f / DD);
    float var  = Q * (1.f / DD) - mean * mean;
    float rstd = rsqrtf(var + 1e-5f);
    float4 wv = ((const float4*)w)[j];
    float4 bv = ((const float4*)b)[j];
    float4 o4;
    o4.x = (v.x - mean) * rstd * wv.x + bv.x;
    o4.y = (v.y - mean) * rstd * wv.y + bv.y;
    o4.z = (v.z - mean) * rstd * wv.z + bv.z;
    o4.w = (v.w - mean) * rstd * wv.w + bv.w;
    ((float4*)(out + (size_t)t * DD))[j] = o4;
}

// ---------------- fused embedding + ln1 ----------------
__global__ void embed_ln_kernel(const int* __restrict__ ids,
                                const float* __restrict__ tok,
                                const float* __restrict__ pe,
                                const float* __restrict__ w,
                                const float* __restrict__ b,
                                float* __restrict__ x,
                                float* __restrict__ xn) {
    int t = blockIdx.x, j = threadIdx.x;
    int id = ids[t];
    float4 a = ((const float4*)(tok + (size_t)id * DD))[j];
    float4 p = ((const float4*)(pe  + (size_t)t  * DD))[j];
    a.x += p.x; a.y += p.y; a.z += p.z; a.w += p.w;
    ((float4*)(x + (size_t)t * DD))[j] = a;
    ln_body(a, w, b, xn, t, j);
}

// ---------------- standalone layernorm (for ln2) ----------------
__global__ void ln_kernel(const float* __restrict__ x,
                          const float* __restrict__ w,
                          const float* __restrict__ b,
                          float* __restrict__ out) {
    int t = blockIdx.x, j = threadIdx.x;
    float4 v = ((const float4*)(x + (size_t)t * DD))[j];
    ln_body(v, w, b, out, t, j);
}

// ---------------- fused combine + next LN ----------------
__global__ void combine_ln_kernel(float* __restrict__ x,
                                  const float* __restrict__ eo,
                                  const int* __restrict__ pos,
                                  const float* __restrict__ gate,
                                  const float* __restrict__ w,
                                  const float* __restrict__ b,
                                  float* __restrict__ out) {
    int t = blockIdx.x, j = threadIdx.x;
    int p0 = pos[2 * t], p1 = pos[2 * t + 1];
    float g0 = gate[2 * t], g1 = gate[2 * t + 1];
    float4 v = ((const float4*)(x + (size_t)t * DD))[j];
    if (p0 >= 0) {
        float4 a = ((const float4*)(eo + (size_t)p0 * DD))[j];
        v.x += g0 * a.x; v.y += g0 * a.y; v.z += g0 * a.z; v.w += g0 * a.w;
    }
    if (p1 >= 0) {
        float4 a = ((const float4*)(eo + (size_t)p1 * DD))[j];
        v.x += g1 * a.x; v.y += g1 * a.y; v.z += g1 * a.z; v.w += g1 * a.w;
    }
    ((float4*)(x + (size_t)t * DD))[j] = v;
    ln_body(v, w, b, out, t, j);
}

// ---------------- RoPE in-place on q,k; 8 warps per block ----------------
__global__ __launch_bounds__(256)
void rope_kernel(float* __restrict__ qkv) {
    int gw = blockIdx.x * 8 + (threadIdx.x >> 5);
    int t = gw >> 4, h = gw & 15;
    int i = threadIdx.x & 31;
    float div = expf((float)(-2 * i) * (logf(10000.f) / 64.f));
    float ang = (float)t * div;
    float s, c;
    sincosf(ang, &s, &c);
#pragma unroll
    for (int which = 0; which < 2; which++) {
        float* b = qkv + (size_t)t * (3 * DD) + which * DD + h * HS;
        float t1 = b[i], t2 = b[i + 32];
        b[i]      = t1 * c - t2 * s;
        b[i + 32] = t2 * c + t1 * s;
    }
}

// ---------------- flash attention; output (H, T, HS) "bhtd" ----------------
// 128 threads / 64 queries per block: two threads per query, each owning 32
// of the 64 V-channels. QK dot + softmax chain duplicated identically in both
// halves; per-channel AV chains unchanged -> BITWISE-identical output.
__global__ __launch_bounds__(128)
void attn_kernel(const float* __restrict__ qkv, float* __restrict__ av) {
    int h = blockIdx.y;
    int qtile = gridDim.x - 1 - blockIdx.x;   // heavy workloads first
    int tid = threadIdx.x;
    int qlane = tid & 63;
    int half = tid >> 6;                      // 0: channels 0-31, 1: 32-63
    int qt = qtile * 64 + qlane;

    __shared__ float4 Ks[64][16];
    __shared__ float4 Vs[64][16];

    float4 qv[16];
    const float4* qrow = (const float4*)(qkv + (size_t)qt * (3 * DD) + h * HS);
#pragma unroll
    for (int i = 0; i < 16; i++) qv[i] = qrow[i];

    ull o2[16];
#pragma unroll
    for (int d = 0; d < 16; d++) o2[d] = 0ULL;
    float m = -1e30f, l = 0.f;

    int nkt = qtile + 1;
    for (int kt = 0; kt < nkt; kt++) {
        __syncthreads();
#pragma unroll
        for (int j = 0; j < 8; j++) {
            int idx = tid + j * 128;
            int s = idx >> 4, c = idx & 15;
            int gs = kt * 64 + s;
            const float4* kr = (const float4*)(qkv + (size_t)gs * (3 * DD) + DD + h * HS);
            const float4* vr = (const float4*)(qkv + (size_t)gs * (3 * DD) + 2 * DD + h * HS);
            Ks[s][c] = kr[c];
            Vs[s][c] = vr[c];
        }
        __syncthreads();

#pragma unroll
        for (int sub = 0; sub < 4; sub++) {
            float sc[16];
            float tmax = -1e30f;
#pragma unroll
            for (int s = 0; s < 16; s++) {
                int ls = sub * 16 + s;
                float acc = 0.f;
#pragma unroll
                for (int i = 0; i < 16; i++) {
                    float4 k4 = Ks[ls][i];
                    acc += qv[i].x * k4.x + qv[i].y * k4.y + qv[i].z * k4.z + qv[i].w * k4.w;
                }
                int gs = kt * 64 + ls;
                acc = (gs <= qt) ? acc * 0.125f : -1e30f;
                sc[s] = acc;
                tmax = fmaxf(tmax, acc);
            }
            float nm = fmaxf(m, tmax);
            float scale = __expf(m - nm);
            l *= scale;
            ull s2 = pack2(scale, scale);
#pragma unroll
            for (int d = 0; d < 16; d++) mul2(o2[d], s2);
#pragma unroll
            for (int s = 0; s < 16; s++) {
                int ls = sub * 16 + s;
                float p = __expf(sc[s] - nm);
                l += p;
                ull p2 = pack2(p, p);
                const ulonglong2* vrow = (const ulonglong2*)&Vs[ls][0];
#pragma unroll
                for (int i = 0; i < 8; i++) {
                    ulonglong2 vv = vrow[half * 8 + i];
                    fma2(o2[i * 2 + 0], p2, vv.x);
                    fma2(o2[i * 2 + 1], p2, vv.y);
                }
            }
            m = nm;
        }
    }
    float inv = 1.f / l;
    float* orow = av + ((size_t)h * TT + qt) * HS + half * 32;
#pragma unroll
    for (int i = 0; i < 8; i++) {
        float4 v;
        float e0, e1, e2, e3;
        unpack2(o2[i * 2 + 0], e0, e1);
        unpack2(o2[i * 2 + 1], e2, e3);
        v.x = e0 * inv; v.y = e1 * inv;
        v.z = e2 * inv; v.w = e3 * inv;
        ((float4*)orow)[i] = v;
    }
}

// ---------------- router: logits, noisy top-2, gates ----------------
__global__ void router_kernel(const float* __restrict__ xn,
                              const float* __restrict__ rw, const float* __restrict__ rb,
                              const float* __restrict__ nw, const float* __restrict__ nb,
                              const float* __restrict__ noise,
                              int* __restrict__ topi, float* __restrict__ gate) {
    int t = blockIdx.x;
    int wid = threadIdx.x >> 5, lane = threadIdx.x & 31;
    __shared__ float noisy[EE];
    const float4* x4 = (const float4*)(xn + (size_t)t * DD);
    const float4* r4 = (const float4*)(rw + (size_t)wid * DD);
    const float4* n4 = (const float4*)(nw + (size_t)wid * DD);
    float a = 0.f, c = 0.f;
    for (int j = lane; j < DD / 4; j += 32) {
        float4 xv = x4[j], rv = r4[j], nv = n4[j];
        a += xv.x * rv.x + xv.y * rv.y + xv.z * rv.z + xv.w * rv.w;
        c += xv.x * nv.x + xv.y * nv.y + xv.z * nv.z + xv.w * nv.w;
    }
#pragma unroll
    for (int o = 16; o > 0; o >>= 1) {
        a += __shfl_xor_sync(0xffffffffu, a, o);
        c += __shfl_xor_sync(0xffffffffu, c, o);
    }
    if (lane == 0) {
        float logit = a + rb[wid];
        float nl = c + nb[wid];
        float sp = (nl > 20.f) ? nl : log1pf(expf(nl));
        noisy[wid] = logit + noise[(size_t)t * EE + wid] * sp;
    }
    __syncthreads();
    if (threadIdx.x == 0) {
        int i0 = 0; float v0 = noisy[0];
#pragma unroll
        for (int e = 1; e < EE; e++) if (noisy[e] > v0) { v0 = noisy[e]; i0 = e; }
        int i1 = -1; float v1 = -1e30f;
#pragma unroll
        for (int e = 0; e < EE; e++) if (e != i0 && noisy[e] > v1) { v1 = noisy[e]; i1 = e; }
        float g0 = 1.f / (1.f + expf(v1 - v0));
        topi[t * 2] = i0; topi[t * 2 + 1] = i1;
        gate[t * 2] = g0; gate[t * 2 + 1] = 1.f - g0;
    }
}

// ---------------- capacity rank / position ----------------
__global__ void rank_kernel(const int* __restrict__ topi, int* __restrict__ pos) {
    int e = threadIdx.x >> 5, lane = threadIdx.x & 31;
    int base = 0;
    for (int c = 0; c < (TT * KK) / 32; c++) {
        int i = c * 32 + lane;
        int ef = topi[i];
        bool mt = (ef == e);
        unsigned msk = __ballot_sync(0xffffffffu, mt);
        if (mt) {
            int r = base + __popc(msk & ((1u << lane) - 1u));
            pos[i] = (r < CAP) ? (e * CAP + r) : -1;
        }
        base += __popc(msk);
    }
}

// ---------------- dispatch gather ----------------
__global__ void dispatch_kernel(const float* __restrict__ xn,
                                const int* __restrict__ pos,
                                float* __restrict__ de) {
    int i = blockIdx.x;
    int p = pos[i];
    if (p < 0) return;
    int t = i >> 1;
    ((float4*)(de + (size_t)p * DD))[threadIdx.x] =
        ((const float4*)(xn + (size_t)t * DD))[threadIdx.x];
}

// ---------------- host side ----------------
static void run_gemm_ffma(const float* A, const float* B, const float* bias,
                          const float* res, float* C, int M, int N, int Kd, int batch,
                          long long aB, long long bB, long long biasB, long long cB,
                          bool relu) {
    dim3 grid(N / 128, M / 128, batch), blk(256);
    if (res) {
        gemm_kernel<false, true><<<grid, blk>>>(A, B, bias, res, C, M, N, Kd, aB, bB, biasB, cB);
    } else if (relu) {
        gemm_kernel<true, false><<<grid, blk>>>(A, B, bias, nullptr, C, M, N, Kd, aB, bB, biasB, cB);
    } else {
        gemm_kernel<false, false><<<grid, blk>>>(A, B, bias, nullptr, C, M, N, Kd, aB, bB, biasB, cB);
    }
}

static void run_gemm_tc(const float* A, const float* B, const float* bias,
                        float* C, int M, int N, int Kd, int batch,
                        long long aB, long long bB, long long biasB, long long cB,
                        bool relu) {
    dim3 grid(N / 64, M / 128, batch), blk(256);
    if (relu)
        gemm_tc3<true><<<grid, blk, GEMM_TC_SMEM>>>(A, B, bias, C, M, N, Kd, aB, bB, biasB, cB);
    else
        gemm_tc3<false><<<grid, blk, GEMM_TC_SMEM>>>(A, B, bias, C, M, N, Kd, aB, bB, biasB, cB);
}

extern "C" void kernel_launch(void* const* d_in, const int* in_sizes, int n_in,
                              void* d_out, int out_size) {
    const int*   ids      = (const int*)  d_in[0];
    const float* noise    = (const float*)d_in[1];
    const float* tok_emb  = (const float*)d_in[2];
    const float* pos_emb  = (const float*)d_in[3];
    const float* ln1_w    = (const float*)d_in[4];
    const float* ln1_b    = (const float*)d_in[5];
    const float* ln2_w    = (const float*)d_in[6];
    const float* ln2_b    = (const float*)d_in[7];
    const float* qkv_w    = (const float*)d_in[8];
    const float* out_w    = (const float*)d_in[9];
    const float* router_w = (const float*)d_in[10];
    const float* router_b = (const float*)d_in[11];
    const float* noise_w  = (const float*)d_in[12];
    const float* noise_b  = (const float*)d_in[13];
    const float* e_w1     = (const float*)d_in[14];
    const float* e_b1     = (const float*)d_in[15];
    const float* e_w2     = (const float*)d_in[16];
    const float* e_b2     = (const float*)d_in[17];
    const float* lnf_w    = (const float*)d_in[18];
    const float* lnf_b    = (const float*)d_in[19];

    static bool attr_set = false;
    if (!attr_set) {
        cudaFuncSetAttribute(gemm_tc3<true>,  cudaFuncAttributeMaxDynamicSharedMemorySize, GEMM_TC_SMEM);
        cudaFuncSetAttribute(gemm_tc3<false>, cudaFuncAttributeMaxDynamicSharedMemorySize, GEMM_TC_SMEM);
        attr_set = true;
    }

    float *x, *xn, *qkv, *av, *de, *h, *eo, *gate;
    int *topi, *pos;
    cudaGetSymbolAddress((void**)&x,    g_x);
    cudaGetSymbolAddress((void**)&xn,   g_xn);
    cudaGetSymbolAddress((void**)&qkv,  g_qkv);
    cudaGetSymbolAddress((void**)&av,   g_av);
    cudaGetSymbolAddress((void**)&de,   g_de);
    cudaGetSymbolAddress((void**)&h,    g_h);
    cudaGetSymbolAddress((void**)&eo,   g_eo);
    cudaGetSymbolAddress((void**)&topi, g_topi);
    cudaGetSymbolAddress((void**)&pos,  g_pos);
    cudaGetSymbolAddress((void**)&gate, g_gate);

    // embed + ln1(layer 0) fused
    embed_ln_kernel<<<TT, 256>>>(ids, tok_emb, pos_emb, ln1_w, ln1_b, x, xn);

    for (int l = 0; l < LL; l++) {
        bool fast_experts = (l == LL - 1);   // post-all-routers -> MMA safe

        // attention block (router-sensitive: bitwise FFMA path); xn = ln1(x)
        run_gemm_ffma(xn, qkv_w + (size_t)l * 3 * DD * DD, nullptr, nullptr, qkv,
                      TT, 3 * DD, DD, 1, 0, 0, 0, 0, false);
        rope_kernel<<<TT * HH / 8, 256>>>(qkv);
        attn_kernel<<<dim3(TT / 64, HH), 128>>>(qkv, av);
        run_gemm_ffma(av, out_w + (size_t)l * DD * DD, nullptr, x, x,
                      TT, DD, DD, 1, 0, 0, 0, 0, false);

        // MoE block
        ln_kernel<<<TT, 256>>>(x, ln2_w + (size_t)l * DD, ln2_b + (size_t)l * DD, xn);
        router_kernel<<<TT, 256>>>(xn,
                                   router_w + (size_t)l * EE * DD, router_b + (size_t)l * EE,
                                   noise_w  + (size_t)l * EE * DD, noise_b  + (size_t)l * EE,
                                   noise + (size_t)l * TT * EE, topi, gate);
        rank_kernel<<<1, 256>>>(topi, pos);
        dispatch_kernel<<<TT * KK, 256>>>(xn, pos, de);
        if (fast_experts) {
            run_gemm_tc(de, e_w1 + (size_t)l * EE * FF * DD, e_b1 + (size_t)l * EE * FF,
                        h, CAP, FF, DD, EE,
                        (long long)CAP * DD, (long long)FF * DD, FF, (long long)CAP * FF, true);
            run_gemm_tc(h, e_w2 + (size_t)l * EE * DD * FF, e_b2 + (size_t)l * EE * DD,
                        eo, CAP, DD, FF, EE,
                        (long long)CAP * FF, (long long)DD * FF, DD, (long long)CAP * DD, false);
        } else {
            run_gemm_ffma(de, e_w1 + (size_t)l * EE * FF * DD, e_b1 + (size_t)l * EE * FF,
                          nullptr, h, CAP, FF, DD, EE,
                          (long long)CAP * DD, (long long)FF * DD, FF, (long long)CAP * FF, true);
            run_gemm_ffma(h, e_w2 + (size_t)l * EE * DD * FF, e_b2 + (size_t)l * EE * DD,
                          nullptr, eo, CAP, DD, FF, EE,
                          (long long)CAP * FF, (long long)DD * FF, DD, (long long)CAP * DD, false);
        }
        // combine + next LN fused (ln1 of next layer, or final lnf -> d_out)
        if (l + 1 < LL) {
            combine_ln_kernel<<<TT, 256>>>(x, eo, pos, gate,
                                           ln1_w + (size_t)(l + 1) * DD,
                                           ln1_b + (size_t)(l + 1) * DD, xn);
        } else {
            combine_ln_kernel<<<TT, 256>>>(x, eo, pos, gate,
                                           lnf_w, lnf_b, (float*)d_out);
        }
    }
}

// round 17
// speedup vs baseline: 1.1078x; 1.0820x over previous
#include <cuda_runtime.h>
#include <cuda_bf16.h>
#include <cstdint>
#include <math.h>

// ---------------- constants ----------------
#define TT   2048
#define DD   1024
#define HH   16
#define HS   64
#define EE   8
#define KK   2
#define LL   2
#define CAP  512
#define FF   4096   // 4*D

// ---------------- scratch (device globals; no allocation allowed) ----------
__device__ float g_x  [TT * DD];
__device__ float g_xn [TT * DD];
__device__ float g_qkv[TT * 3 * DD];
__device__ float g_av [TT * DD];
__device__ float g_de [EE * CAP * DD];
__device__ float g_h  [EE * CAP * FF];
__device__ float g_eo [EE * CAP * DD];
__device__ int   g_topi[TT * KK];
__device__ int   g_pos [TT * KK];
__device__ float g_gate[TT * KK];

// ---------------- packed f32x2 helpers ----------------
typedef unsigned long long ull;
__device__ __forceinline__ ull pack2(float lo, float hi) {
    ull r;
    asm("mov.b64 %0, {%1, %2};" : "=l"(r) : "f"(lo), "f"(hi));
    return r;
}
__device__ __forceinline__ void unpack2(ull v, float& lo, float& hi) {
    asm("mov.b64 {%0, %1}, %2;" : "=f"(lo), "=f"(hi) : "l"(v));
}
__device__ __forceinline__ void fma2(ull& d, ull a, ull b) {
    asm("fma.rn.f32x2 %0, %1, %2, %0;" : "+l"(d) : "l"(a), "l"(b));
}
__device__ __forceinline__ void mul2(ull& d, ull a) {
    asm("mul.rn.f32x2 %0, %0, %1;" : "+l"(d) : "l"(a));
}

__device__ __forceinline__ uint32_t smem_u32(const void* p) {
    uint32_t a;
    asm("{ .reg .u64 t; cvta.to.shared.u64 t, %1; cvt.u32.u64 %0, t; }" : "=r"(a) : "l"(p));
    return a;
}

// =====================================================================
// fp32 GEMM, packed f32x2 FMA, double-buffered (bitwise == round 3 ->
// router decisions preserved). C = A(MxK)*B(NxK)^T (+bias)(+res)(relu).
// =====================================================================
template <bool RELU, bool RES>
__global__ __launch_bounds__(256)
void gemm_kernel(const float* __restrict__ A, const float* __restrict__ Bm,
                 const float* __restrict__ bias, const float* res,
                 float* C,
                 int M, int N, int Kd,
                 long long aB, long long bB, long long biasB, long long cB) {
    int bz = blockIdx.z;
    A  += (long long)bz * aB;
    Bm += (long long)bz * bB;
    C  += (long long)bz * cB;
    if (bias) bias += (long long)bz * biasB;

    int rowBase = blockIdx.y * 128;
    int colBase = blockIdx.x * 128;

    __shared__ float As[2][16][128];
    __shared__ float Bs[2][16][128];

    int tid = threadIdx.x;
    int tx = tid & 15, ty = tid >> 4;
    int lrow = tid >> 2;
    int lcol = (tid & 3) * 4;

    const float* Arow0 = A  + (size_t)(rowBase + lrow)      * Kd + lcol;
    const float* Arow1 = A  + (size_t)(rowBase + lrow + 64) * Kd + lcol;
    const float* Brow0 = Bm + (size_t)(colBase + lrow)      * Kd + lcol;
    const float* Brow1 = Bm + (size_t)(colBase + lrow + 64) * Kd + lcol;

    ull acc2[8][4];
#pragma unroll
    for (int i = 0; i < 8; i++)
#pragma unroll
        for (int j = 0; j < 4; j++) acc2[i][j] = 0ULL;

    float4 ra0, ra1, rb0, rb1;

    ra0 = *(const float4*)(Arow0);
    ra1 = *(const float4*)(Arow1);
    rb0 = *(const float4*)(Brow0);
    rb1 = *(const float4*)(Brow1);
    {
        float* a0 = &As[0][lcol][lrow];
        a0[0 * 128] = ra0.x; a0[1 * 128] = ra0.y; a0[2 * 128] = ra0.z; a0[3 * 128] = ra0.w;
        float* a1 = &As[0][lcol][lrow + 64];
        a1[0 * 128] = ra1.x; a1[1 * 128] = ra1.y; a1[2 * 128] = ra1.z; a1[3 * 128] = ra1.w;
        float* b0 = &Bs[0][lcol][lrow];
        b0[0 * 128] = rb0.x; b0[1 * 128] = rb0.y; b0[2 * 128] = rb0.z; b0[3 * 128] = rb0.w;
        float* b1 = &Bs[0][lcol][lrow + 64];
        b1[0 * 128] = rb1.x; b1[1 * 128] = rb1.y; b1[2 * 128] = rb1.z; b1[3 * 128] = rb1.w;
    }
    __syncthreads();

    const int nCh = Kd >> 4;
    for (int ch = 0; ch < nCh; ++ch) {
        int cur = ch & 1;
        if (ch + 1 < nCh) {
            int k0 = (ch + 1) << 4;
            ra0 = *(const float4*)(Arow0 + k0);
            ra1 = *(const float4*)(Arow1 + k0);
            rb0 = *(const float4*)(Brow0 + k0);
            rb1 = *(const float4*)(Brow1 + k0);
        }
#pragma unroll
        for (int kk = 0; kk < 16; kk++) {
            float4 a0 = *(const float4*)&As[cur][kk][ty * 4];
            float4 a1 = *(const float4*)&As[cur][kk][64 + ty * 4];
            ulonglong2 bb0 = *(const ulonglong2*)&Bs[cur][kk][tx * 4];
            ulonglong2 bb1 = *(const ulonglong2*)&Bs[cur][kk][64 + tx * 4];
            float ar[8] = {a0.x, a0.y, a0.z, a0.w, a1.x, a1.y, a1.z, a1.w};
            ull b2[4] = {bb0.x, bb0.y, bb1.x, bb1.y};
#pragma unroll
            for (int i = 0; i < 8; i++) {
                ull a2 = pack2(ar[i], ar[i]);
#pragma unroll
                for (int j = 0; j < 4; j++) fma2(acc2[i][j], a2, b2[j]);
            }
        }
        if (ch + 1 < nCh) {
            int nxt = cur ^ 1;
            float* a0 = &As[nxt][lcol][lrow];
            a0[0 * 128] = ra0.x; a0[1 * 128] = ra0.y; a0[2 * 128] = ra0.z; a0[3 * 128] = ra0.w;
            float* a1 = &As[nxt][lcol][lrow + 64];
            a1[0 * 128] = ra1.x; a1[1 * 128] = ra1.y; a1[2 * 128] = ra1.z; a1[3 * 128] = ra1.w;
            float* b0 = &Bs[nxt][lcol][lrow];
            b0[0 * 128] = rb0.x; b0[1 * 128] = rb0.y; b0[2 * 128] = rb0.z; b0[3 * 128] = rb0.w;
            float* b1 = &Bs[nxt][lcol][lrow + 64];
            b1[0 * 128] = rb1.x; b1[1 * 128] = rb1.y; b1[2 * 128] = rb1.z; b1[3 * 128] = rb1.w;
            __syncthreads();
        }
    }

#pragma unroll
    for (int i = 0; i < 8; i++) {
        int r = rowBase + ((i < 4) ? (ty * 4 + i) : (64 + ty * 4 + (i - 4)));
#pragma unroll
        for (int jj = 0; jj < 2; jj++) {
            int c = colBase + jj * 64 + tx * 4;
            float4 v;
            unpack2(acc2[i][jj * 2 + 0], v.x, v.y);
            unpack2(acc2[i][jj * 2 + 1], v.z, v.w);
            if (bias) {
                v.x += bias[c]; v.y += bias[c + 1];
                v.z += bias[c + 2]; v.w += bias[c + 3];
            }
            if (RES) {
                float4 rv = *(const float4*)(res + (size_t)r * N + c);
                v.x = rv.x + v.x; v.y = rv.y + v.y;
                v.z = rv.z + v.z; v.w = rv.w + v.w;
            }
            if (RELU) {
                v.x = fmaxf(v.x, 0.f); v.y = fmaxf(v.y, 0.f);
                v.z = fmaxf(v.z, 0.f); v.w = fmaxf(v.w, 0.f);
            }
            *(float4*)(C + (size_t)r * N + c) = v;
        }
    }
}

// =====================================================================
// mma.sync bf16 2-limb / 3-term GEMM, fragment-deduplicated inner loop.
// CTA tile 128x64, K-chunk 32, double-buffered, 2 CTAs/SM.
// Decision-free GEMMs only (layer-2 expert FFN).
// =====================================================================
#define LDSM_X4(r, addr)                                                        \
    asm volatile("ldmatrix.sync.aligned.m8n8.x4.shared.b16 {%0,%1,%2,%3}, [%4];"\
        : "=r"((r)[0]), "=r"((r)[1]), "=r"((r)[2]), "=r"((r)[3]) : "r"(addr))

#define MMA_BF16(d, a, b0, b1)                                                  \
    asm volatile("mma.sync.aligned.m16n8k16.row.col.f32.bf16.bf16.f32 "         \
        "{%0,%1,%2,%3}, {%4,%5,%6,%7}, {%8,%9}, {%0,%1,%2,%3};"                 \
        : "+f"((d)[0]), "+f"((d)[1]), "+f"((d)[2]), "+f"((d)[3])                \
        : "r"((a)[0]), "r"((a)[1]), "r"((a)[2]), "r"((a)[3]), "r"(b0), "r"(b1))

#define TSTRIDE 80
#define ATILE (128 * TSTRIDE)
#define BTILE (64 * TSTRIDE)
#define BUFSZ (2 * ATILE + 2 * BTILE)
#define TA(buf, limb) ((buf) * BUFSZ + (limb) * ATILE)
#define TB(buf, limb) ((buf) * BUFSZ + 2 * ATILE + (limb) * BTILE)
#define GEMM_TC_SMEM (2 * BUFSZ)               // 61440 B -> 2 CTAs/SM

__device__ __forceinline__ void split8(const float4& f0, const float4& f1,
                                       uint32_t* ph, uint32_t* pm) {
    float v[8] = {f0.x, f0.y, f0.z, f0.w, f1.x, f1.y, f1.z, f1.w};
#pragma unroll
    for (int q = 0; q < 4; ++q) {
        float a = v[2 * q], b = v[2 * q + 1];
        __nv_bfloat162 hb = __float22bfloat162_rn(make_float2(a, b));
        ph[q] = *(uint32_t*)&hb;
        float ra = a - __bfloat162float(hb.x);
        float rb = b - __bfloat162float(hb.y);
        __nv_bfloat162 mb = __float22bfloat162_rn(make_float2(ra, rb));
        pm[q] = *(uint32_t*)&mb;
    }
}

__device__ __forceinline__ void ldgA(const float* __restrict__ src, int ldk,
                                     int k0, float4* f, int tid) {
#pragma unroll
    for (int it = 0; it < 2; ++it) {
        int G = it * 256 + tid;
        int row = G >> 2, cg = G & 3;
        const float* p = src + (size_t)row * ldk + k0 + cg * 8;
        f[it * 2 + 0] = *(const float4*)p;
        f[it * 2 + 1] = *(const float4*)(p + 4);
    }
}
__device__ __forceinline__ void stsA(const float4* f, char* __restrict__ sm,
                                     int hi_off, int mi_off, int tid) {
#pragma unroll
    for (int it = 0; it < 2; ++it) {
        int G = it * 256 + tid;
        int row = G >> 2, cg = G & 3;
        uint32_t ph[4], pm[4];
        split8(f[it * 2 + 0], f[it * 2 + 1], ph, pm);
        int off = row * TSTRIDE + cg * 16;
        *(uint4*)(sm + hi_off + off) = make_uint4(ph[0], ph[1], ph[2], ph[3]);
        *(uint4*)(sm + mi_off + off) = make_uint4(pm[0], pm[1], pm[2], pm[3]);
    }
}
__device__ __forceinline__ void ldgB(const float* __restrict__ src, int ldk,
                                     int k0, float4* f, int tid) {
    int row = tid >> 2, cg = tid & 3;
    const float* p = src + (size_t)row * ldk + k0 + cg * 8;
    f[0] = *(const float4*)p;
    f[1] = *(const float4*)(p + 4);
}
__device__ __forceinline__ void stsB(const float4* f, char* __restrict__ sm,
                                     int hi_off, int mi_off, int tid) {
    int row = tid >> 2, cg = tid & 3;
    uint32_t ph[4], pm[4];
    split8(f[0], f[1], ph, pm);
    int off = row * TSTRIDE + cg * 16;
    *(uint4*)(sm + hi_off + off) = make_uint4(ph[0], ph[1], ph[2], ph[3]);
    *(uint4*)(sm + mi_off + off) = make_uint4(pm[0], pm[1], pm[2], pm[3]);
}

template <bool RELU>
__global__ __launch_bounds__(256, 2)
void gemm_tc3(const float* __restrict__ Ag, const float* __restrict__ Bg,
              const float* __restrict__ bias, float* __restrict__ C,
              int M, int N, int Kd,
              long long aB, long long bB, long long biasB, long long cB) {
    extern __shared__ char smem[];
    uint32_t sb = smem_u32(smem);
    int tid = threadIdx.x;
    int wid = tid >> 5, lane = tid & 31;
    int wm = wid >> 2, wn = wid & 3;

    int bz = blockIdx.z;
    int rowBase = blockIdx.y * 128;
    int colBase = blockIdx.x * 64;
    const float* A = Ag + (long long)bz * aB + (size_t)rowBase * Kd;
    const float* B = Bg + (long long)bz * bB + (size_t)colBase * Kd;
    const float* bi = bias ? (bias + (long long)bz * biasB) : nullptr;
    float* Cp = C + (long long)bz * cB;

    float acc[4][2][4];
#pragma unroll
    for (int i = 0; i < 4; i++)
#pragma unroll
        for (int j = 0; j < 2; j++)
#pragma unroll
            for (int q = 0; q < 4; q++) acc[i][j][q] = 0.f;

    int lrow = lane & 15;
    int lhalf = (lane >> 4) * 8;

    float4 fa[4], fb[2];

    ldgA(A, Kd, 0, fa, tid);
    ldgB(B, Kd, 0, fb, tid);
    stsA(fa, smem, TA(0, 0), TA(0, 1), tid);
    stsB(fb, smem, TB(0, 0), TB(0, 1), tid);
    __syncthreads();

    const int nCh = Kd >> 5;
    for (int ch = 0; ch < nCh; ++ch) {
        int cur = ch & 1;
        if (ch + 1 < nCh) {
            int k0 = (ch + 1) * 32;
            ldgA(A, Kd, k0, fa, tid);
            ldgB(B, Kd, k0, fb, tid);
        }
        uint32_t aHi = sb + TA(cur, 0), aMi = sb + TA(cur, 1);
        uint32_t bHi = sb + TB(cur, 0), bMi = sb + TB(cur, 1);
#pragma unroll
        for (int ks = 0; ks < 2; ++ks) {
            uint32_t af[4][4], bfh[4], bfm[4];
            int kcol = (ks * 16 + lhalf) * 2;
            LDSM_X4(bfh, bHi + (wn * 16 + lrow) * TSTRIDE + kcol);
            LDSM_X4(bfm, bMi + (wn * 16 + lrow) * TSTRIDE + kcol);
#pragma unroll
            for (int i = 0; i < 4; ++i)
                LDSM_X4(af[i], aHi + (wm * 64 + i * 16 + lrow) * TSTRIDE + kcol);
#pragma unroll
            for (int i = 0; i < 4; ++i)
#pragma unroll
                for (int j = 0; j < 2; ++j)
                    MMA_BF16(acc[i][j], af[i], bfh[j], bfh[j + 2]);   // hh
#pragma unroll
            for (int i = 0; i < 4; ++i)
#pragma unroll
                for (int j = 0; j < 2; ++j)
                    MMA_BF16(acc[i][j], af[i], bfm[j], bfm[j + 2]);   // hm
#pragma unroll
            for (int i = 0; i < 4; ++i)
                LDSM_X4(af[i], aMi + (wm * 64 + i * 16 + lrow) * TSTRIDE + kcol);
#pragma unroll
            for (int i = 0; i < 4; ++i)
#pragma unroll
                for (int j = 0; j < 2; ++j)
                    MMA_BF16(acc[i][j], af[i], bfh[j], bfh[j + 2]);   // mh
        }
        if (ch + 1 < nCh) {
            int nxt = cur ^ 1;
            stsA(fa, smem, TA(nxt, 0), TA(nxt, 1), tid);
            stsB(fb, smem, TB(nxt, 0), TB(nxt, 1), tid);
            __syncthreads();
        }
    }

#pragma unroll
    for (int i = 0; i < 4; ++i) {
        int r0 = rowBase + wm * 64 + i * 16 + (lane >> 2);
#pragma unroll
        for (int j = 0; j < 2; ++j) {
            int c = colBase + wn * 16 + j * 8 + (lane & 3) * 2;
            float2 v0 = make_float2(acc[i][j][0], acc[i][j][1]);
            float2 v1 = make_float2(acc[i][j][2], acc[i][j][3]);
            if (bi) {
                float2 bv = *(const float2*)(bi + c);
                v0.x += bv.x; v0.y += bv.y;
                v1.x += bv.x; v1.y += bv.y;
            }
            if (RELU) {
                v0.x = fmaxf(v0.x, 0.f); v0.y = fmaxf(v0.y, 0.f);
                v1.x = fmaxf(v1.x, 0.f); v1.y = fmaxf(v1.y, 0.f);
            }
            *(float2*)(Cp + (size_t)r0 * N + c)       = v0;
            *(float2*)(Cp + (size_t)(r0 + 8) * N + c) = v1;
        }
    }
}

// ---------------- LN body shared by fused kernels ----------------
__device__ __forceinline__ void ln_body(float4 v, const float* __restrict__ w,
                                        const float* __restrict__ b,
                                        float* __restrict__ out, int t, int j) {
    float s = v.x + v.y + v.z + v.w;
    float q = v.x * v.x + v.y * v.y + v.z * v.z + v.w * v.w;
#pragma unroll
    for (int o = 16; o > 0; o >>= 1) {
        s += __shfl_xor_sync(0xffffffffu, s, o);
        q += __shfl_xor_sync(0xffffffffu, q, o);
    }
    __shared__ float ss[8], sq[8];
    if ((j & 31) == 0) { ss[j >> 5] = s; sq[j >> 5] = q; }
    __syncthreads();
    float S = 0.f, Q = 0.f;
#pragma unroll
    for (int k = 0; k < 8; k++) { S += ss[k]; Q += sq[k]; }
    float mean = S * (1.f / DD);
    float var  = Q * (1.f / DD) - mean * mean;
    float rstd = rsqrtf(var + 1e-5f);
    float4 wv = ((const float4*)w)[j];
    float4 bv = ((const float4*)b)[j];
    float4 o4;
    o4.x = (v.x - mean) * rstd * wv.x + bv.x;
    o4.y = (v.y - mean) * rstd * wv.y + bv.y;
    o4.z = (v.z - mean) * rstd * wv.z + bv.z;
    o4.w = (v.w - mean) * rstd * wv.w + bv.w;
    ((float4*)(out + (size_t)t * DD))[j] = o4;
}

// ---------------- fused embedding + ln1 ----------------
__global__ void embed_ln_kernel(const int* __restrict__ ids,
                                const float* __restrict__ tok,
                                const float* __restrict__ pe,
                                const float* __restrict__ w,
                                const float* __restrict__ b,
                                float* __restrict__ x,
                                float* __restrict__ xn) {
    int t = blockIdx.x, j = threadIdx.x;
    int id = ids[t];
    float4 a = ((const float4*)(tok + (size_t)id * DD))[j];
    float4 p = ((const float4*)(pe  + (size_t)t  * DD))[j];
    a.x += p.x; a.y += p.y; a.z += p.z; a.w += p.w;
    ((float4*)(x + (size_t)t * DD))[j] = a;
    ln_body(a, w, b, xn, t, j);
}

// ---------------- standalone layernorm (for ln2) ----------------
__global__ void ln_kernel(const float* __restrict__ x,
                          const float* __restrict__ w,
                          const float* __restrict__ b,
                          float* __restrict__ out) {
    int t = blockIdx.x, j = threadIdx.x;
    float4 v = ((const float4*)(x + (size_t)t * DD))[j];
    ln_body(v, w, b, out, t, j);
}

// ---------------- fused combine + next LN ----------------
__global__ void combine_ln_kernel(float* __restrict__ x,
                                  const float* __restrict__ eo,
                                  const int* __restrict__ pos,
                                  const float* __restrict__ gate,
                                  const float* __restrict__ w,
                                  const float* __restrict__ b,
                                  float* __restrict__ out) {
    int t = blockIdx.x, j = threadIdx.x;
    int p0 = pos[2 * t], p1 = pos[2 * t + 1];
    float g0 = gate[2 * t], g1 = gate[2 * t + 1];
    float4 v = ((const float4*)(x + (size_t)t * DD))[j];
    if (p0 >= 0) {
        float4 a = ((const float4*)(eo + (size_t)p0 * DD))[j];
        v.x += g0 * a.x; v.y += g0 * a.y; v.z += g0 * a.z; v.w += g0 * a.w;
    }
    if (p1 >= 0) {
        float4 a = ((const float4*)(eo + (size_t)p1 * DD))[j];
        v.x += g1 * a.x; v.y += g1 * a.y; v.z += g1 * a.z; v.w += g1 * a.w;
    }
    ((float4*)(x + (size_t)t * DD))[j] = v;
    ln_body(v, w, b, out, t, j);
}

// ---------------- RoPE in-place on q,k; 8 warps per block ----------------
__global__ __launch_bounds__(256)
void rope_kernel(float* __restrict__ qkv) {
    int gw = blockIdx.x * 8 + (threadIdx.x >> 5);
    int t = gw >> 4, h = gw & 15;
    int i = threadIdx.x & 31;
    float div = expf((float)(-2 * i) * (logf(10000.f) / 64.f));
    float ang = (float)t * div;
    float s, c;
    sincosf(ang, &s, &c);
#pragma unroll
    for (int which = 0; which < 2; which++) {
        float* b = qkv + (size_t)t * (3 * DD) + which * DD + h * HS;
        float t1 = b[i], t2 = b[i + 32];
        b[i]      = t1 * c - t2 * s;
        b[i + 32] = t2 * c + t1 * s;
    }
}

// ---------------- flash attention; output (H, T, HS) "bhtd" ----------------
// 128 threads / 64 queries per block (two threads per query, 32 V-channels
// each). __launch_bounds__(128,3): force regs <= ~170 so 3 blocks (12 warps)
// co-reside per SM. Register allocation does not change arithmetic ->
// BITWISE-identical output.
__global__ __launch_bounds__(128, 3)
void attn_kernel(const float* __restrict__ qkv, float* __restrict__ av) {
    int h = blockIdx.y;
    int qtile = gridDim.x - 1 - blockIdx.x;   // heavy workloads first
    int tid = threadIdx.x;
    int qlane = tid & 63;
    int half = tid >> 6;                      // 0: channels 0-31, 1: 32-63
    int qt = qtile * 64 + qlane;

    __shared__ float4 Ks[64][16];
    __shared__ float4 Vs[64][16];

    float4 qv[16];
    const float4* qrow = (const float4*)(qkv + (size_t)qt * (3 * DD) + h * HS);
#pragma unroll
    for (int i = 0; i < 16; i++) qv[i] = qrow[i];

    ull o2[16];
#pragma unroll
    for (int d = 0; d < 16; d++) o2[d] = 0ULL;
    float m = -1e30f, l = 0.f;

    int nkt = qtile + 1;
    for (int kt = 0; kt < nkt; kt++) {
        __syncthreads();
#pragma unroll
        for (int j = 0; j < 8; j++) {
            int idx = tid + j * 128;
            int s = idx >> 4, c = idx & 15;
            int gs = kt * 64 + s;
            const float4* kr = (const float4*)(qkv + (size_t)gs * (3 * DD) + DD + h * HS);
            const float4* vr = (const float4*)(qkv + (size_t)gs * (3 * DD) + 2 * DD + h * HS);
            Ks[s][c] = kr[c];
            Vs[s][c] = vr[c];
        }
        __syncthreads();

#pragma unroll
        for (int sub = 0; sub < 4; sub++) {
            float sc[16];
            float tmax = -1e30f;
#pragma unroll
            for (int s = 0; s < 16; s++) {
                int ls = sub * 16 + s;
                float acc = 0.f;
#pragma unroll
                for (int i = 0; i < 16; i++) {
                    float4 k4 = Ks[ls][i];
                    acc += qv[i].x * k4.x + qv[i].y * k4.y + qv[i].z * k4.z + qv[i].w * k4.w;
                }
                int gs = kt * 64 + ls;
                acc = (gs <= qt) ? acc * 0.125f : -1e30f;
                sc[s] = acc;
                tmax = fmaxf(tmax, acc);
            }
            float nm = fmaxf(m, tmax);
            float scale = __expf(m - nm);
            l *= scale;
            ull s2 = pack2(scale, scale);
#pragma unroll
            for (int d = 0; d < 16; d++) mul2(o2[d], s2);
#pragma unroll
            for (int s = 0; s < 16; s++) {
                int ls = sub * 16 + s;
                float p = __expf(sc[s] - nm);
                l += p;
                ull p2 = pack2(p, p);
                const ulonglong2* vrow = (const ulonglong2*)&Vs[ls][0];
#pragma unroll
                for (int i = 0; i < 8; i++) {
                    ulonglong2 vv = vrow[half * 8 + i];
                    fma2(o2[i * 2 + 0], p2, vv.x);
                    fma2(o2[i * 2 + 1], p2, vv.y);
                }
            }
            m = nm;
        }
    }
    float inv = 1.f / l;
    float* orow = av + ((size_t)h * TT + qt) * HS + half * 32;
#pragma unroll
    for (int i = 0; i < 8; i++) {
        float4 v;
        float e0, e1, e2, e3;
        unpack2(o2[i * 2 + 0], e0, e1);
        unpack2(o2[i * 2 + 1], e2, e3);
        v.x = e0 * inv; v.y = e1 * inv;
        v.z = e2 * inv; v.w = e3 * inv;
        ((float4*)orow)[i] = v;
    }
}

// ---------------- router: logits, noisy top-2, gates ----------------
__global__ void router_kernel(const float* __restrict__ xn,
                              const float* __restrict__ rw, const float* __restrict__ rb,
                              const float* __restrict__ nw, const float* __restrict__ nb,
                              const float* __restrict__ noise,
                              int* __restrict__ topi, float* __restrict__ gate) {
    int t = blockIdx.x;
    int wid = threadIdx.x >> 5, lane = threadIdx.x & 31;
    __shared__ float noisy[EE];
    const float4* x4 = (const float4*)(xn + (size_t)t * DD);
    const float4* r4 = (const float4*)(rw + (size_t)wid * DD);
    const float4* n4 = (const float4*)(nw + (size_t)wid * DD);
    float a = 0.f, c = 0.f;
    for (int j = lane; j < DD / 4; j += 32) {
        float4 xv = x4[j], rv = r4[j], nv = n4[j];
        a += xv.x * rv.x + xv.y * rv.y + xv.z * rv.z + xv.w * rv.w;
        c += xv.x * nv.x + xv.y * nv.y + xv.z * nv.z + xv.w * nv.w;
    }
#pragma unroll
    for (int o = 16; o > 0; o >>= 1) {
        a += __shfl_xor_sync(0xffffffffu, a, o);
        c += __shfl_xor_sync(0xffffffffu, c, o);
    }
    if (lane == 0) {
        float logit = a + rb[wid];
        float nl = c + nb[wid];
        float sp = (nl > 20.f) ? nl : log1pf(expf(nl));
        noisy[wid] = logit + noise[(size_t)t * EE + wid] * sp;
    }
    __syncthreads();
    if (threadIdx.x == 0) {
        int i0 = 0; float v0 = noisy[0];
#pragma unroll
        for (int e = 1; e < EE; e++) if (noisy[e] > v0) { v0 = noisy[e]; i0 = e; }
        int i1 = -1; float v1 = -1e30f;
#pragma unroll
        for (int e = 0; e < EE; e++) if (e != i0 && noisy[e] > v1) { v1 = noisy[e]; i1 = e; }
        float g0 = 1.f / (1.f + expf(v1 - v0));
        topi[t * 2] = i0; topi[t * 2 + 1] = i1;
        gate[t * 2] = g0; gate[t * 2 + 1] = 1.f - g0;
    }
}

// ---------------- capacity rank / position ----------------
__global__ void rank_kernel(const int* __restrict__ topi, int* __restrict__ pos) {
    int e = threadIdx.x >> 5, lane = threadIdx.x & 31;
    int base = 0;
    for (int c = 0; c < (TT * KK) / 32; c++) {
        int i = c * 32 + lane;
        int ef = topi[i];
        bool mt = (ef == e);
        unsigned msk = __ballot_sync(0xffffffffu, mt);
        if (mt) {
            int r = base + __popc(msk & ((1u << lane) - 1u));
            pos[i] = (r < CAP) ? (e * CAP + r) : -1;
        }
        base += __popc(msk);
    }
}

// ---------------- dispatch gather ----------------
__global__ void dispatch_kernel(const float* __restrict__ xn,
                                const int* __restrict__ pos,
                                float* __restrict__ de) {
    int i = blockIdx.x;
    int p = pos[i];
    if (p < 0) return;
    int t = i >> 1;
    ((float4*)(de + (size_t)p * DD))[threadIdx.x] =
        ((const float4*)(xn + (size_t)t * DD))[threadIdx.x];
}

// ---------------- host side ----------------
static void run_gemm_ffma(const float* A, const float* B, const float* bias,
                          const float* res, float* C, int M, int N, int Kd, int batch,
                          long long aB, long long bB, long long biasB, long long cB,
                          bool relu) {
    dim3 grid(N / 128, M / 128, batch), blk(256);
    if (res) {
        gemm_kernel<false, true><<<grid, blk>>>(A, B, bias, res, C, M, N, Kd, aB, bB, biasB, cB);
    } else if (relu) {
        gemm_kernel<true, false><<<grid, blk>>>(A, B, bias, nullptr, C, M, N, Kd, aB, bB, biasB, cB);
    } else {
        gemm_kernel<false, false><<<grid, blk>>>(A, B, bias, nullptr, C, M, N, Kd, aB, bB, biasB, cB);
    }
}

static void run_gemm_tc(const float* A, const float* B, const float* bias,
                        float* C, int M, int N, int Kd, int batch,
                        long long aB, long long bB, long long biasB, long long cB,
                        bool relu) {
    dim3 grid(N / 64, M / 128, batch), blk(256);
    if (relu)
        gemm_tc3<true><<<grid, blk, GEMM_TC_SMEM>>>(A, B, bias, C, M, N, Kd, aB, bB, biasB, cB);
    else
        gemm_tc3<false><<<grid, blk, GEMM_TC_SMEM>>>(A, B, bias, C, M, N, Kd, aB, bB, biasB, cB);
}

extern "C" void kernel_launch(void* const* d_in, const int* in_sizes, int n_in,
                              void* d_out, int out_size) {
    const int*   ids      = (const int*)  d_in[0];
    const float* noise    = (const float*)d_in[1];
    const float* tok_emb  = (const float*)d_in[2];
    const float* pos_emb  = (const float*)d_in[3];
    const float* ln1_w    = (const float*)d_in[4];
    const float* ln1_b    = (const float*)d_in[5];
    const float* ln2_w    = (const float*)d_in[6];
    const float* ln2_b    = (const float*)d_in[7];
    const float* qkv_w    = (const float*)d_in[8];
    const float* out_w    = (const float*)d_in[9];
    const float* router_w = (const float*)d_in[10];
    const float* router_b = (const float*)d_in[11];
    const float* noise_w  = (const float*)d_in[12];
    const float* noise_b  = (const float*)d_in[13];
    const float* e_w1     = (const float*)d_in[14];
    const float* e_b1     = (const float*)d_in[15];
    const float* e_w2     = (const float*)d_in[16];
    const float* e_b2     = (const float*)d_in[17];
    const float* lnf_w    = (const float*)d_in[18];
    const float* lnf_b    = (const float*)d_in[19];

    static bool attr_set = false;
    if (!attr_set) {
        cudaFuncSetAttribute(gemm_tc3<true>,  cudaFuncAttributeMaxDynamicSharedMemorySize, GEMM_TC_SMEM);
        cudaFuncSetAttribute(gemm_tc3<false>, cudaFuncAttributeMaxDynamicSharedMemorySize, GEMM_TC_SMEM);
        attr_set = true;
    }

    float *x, *xn, *qkv, *av, *de, *h, *eo, *gate;
    int *topi, *pos;
    cudaGetSymbolAddress((void**)&x,    g_x);
    cudaGetSymbolAddress((void**)&xn,   g_xn);
    cudaGetSymbolAddress((void**)&qkv,  g_qkv);
    cudaGetSymbolAddress((void**)&av,   g_av);
    cudaGetSymbolAddress((void**)&de,   g_de);
    cudaGetSymbolAddress((void**)&h,    g_h);
    cudaGetSymbolAddress((void**)&eo,   g_eo);
    cudaGetSymbolAddress((void**)&topi, g_topi);
    cudaGetSymbolAddress((void**)&pos,  g_pos);
    cudaGetSymbolAddress((void**)&gate, g_gate);

    // embed + ln1(layer 0) fused
    embed_ln_kernel<<<TT, 256>>>(ids, tok_emb, pos_emb, ln1_w, ln1_b, x, xn);

    for (int l = 0; l < LL; l++) {
        bool fast_experts = (l == LL - 1);   // post-all-routers -> MMA safe

        // attention block (router-sensitive: bitwise FFMA path); xn = ln1(x)
        run_gemm_ffma(xn, qkv_w + (size_t)l * 3 * DD * DD, nullptr, nullptr, qkv,
                      TT, 3 * DD, DD, 1, 0, 0, 0, 0, false);
        rope_kernel<<<TT * HH / 8, 256>>>(qkv);
        attn_kernel<<<dim3(TT / 64, HH), 128>>>(qkv, av);
        run_gemm_ffma(av, out_w + (size_t)l * DD * DD, nullptr, x, x,
                      TT, DD, DD, 1, 0, 0, 0, 0, false);

        // MoE block
        ln_kernel<<<TT, 256>>>(x, ln2_w + (size_t)l * DD, ln2_b + (size_t)l * DD, xn);
        router_kernel<<<TT, 256>>>(xn,
                                   router_w + (size_t)l * EE * DD, router_b + (size_t)l * EE,
                                   noise_w  + (size_t)l * EE * DD, noise_b  + (size_t)l * EE,
                                   noise + (size_t)l * TT * EE, topi, gate);
        rank_kernel<<<1, 256>>>(topi, pos);
        dispatch_kernel<<<TT * KK, 256>>>(xn, pos, de);
        if (fast_experts) {
            run_gemm_tc(de, e_w1 + (size_t)l * EE * FF * DD, e_b1 + (size_t)l * EE * FF,
                        h, CAP, FF, DD, EE,
                        (long long)CAP * DD, (long long)FF * DD, FF, (long long)CAP * FF, true);
            run_gemm_tc(h, e_w2 + (size_t)l * EE * DD * FF, e_b2 + (size_t)l * EE * DD,
                        eo, CAP, DD, FF, EE,
                        (long long)CAP * FF, (long long)DD * FF, DD, (long long)CAP * DD, false);
        } else {
            run_gemm_ffma(de, e_w1 + (size_t)l * EE * FF * DD, e_b1 + (size_t)l * EE * FF,
                          nullptr, h, CAP, FF, DD, EE,
                          (long long)CAP * DD, (long long)FF * DD, FF, (long long)CAP * FF, true);
            run_gemm_ffma(h, e_w2 + (size_t)l * EE * DD * FF, e_b2 + (size_t)l * EE * DD,
                          nullptr, eo, CAP, DD, FF, EE,
                          (long long)CAP * FF, (long long)DD * FF, DD, (long long)CAP * DD, false);
        }
        // combine + next LN fused (ln1 of next layer, or final lnf -> d_out)
        if (l + 1 < LL) {
            combine_ln_kernel<<<TT, 256>>>(x, eo, pos, gate,
                                           ln1_w + (size_t)(l + 1) * DD,
                                           ln1_b + (size_t)(l + 1) * DD, xn);
        } else {
            combine_ln_kernel<<<TT, 256>>>(x, eo, pos, gate,
                                           lnf_w, lnf_b, (float*)d_out);
        }
    }
}